// round 1
// baseline (speedup 1.0000x reference)
#include <cuda_runtime.h>
#include <math.h>

// Problem constants
#define Nn   4096
#define Qq   2048
#define LDIM 8192
#define NB   64
#define NP   (Qq/NB)   // 32

#define EULERC 0.5772156649015329
#define CC     0.7796968012336761   // sqrt(6)/pi
#define C2C    0.6079271018540267   // 6/pi^2

// ---------------- device scratch (static, allocation-free) ----------------
__device__ float  g_zs[Nn];
__device__ double g_sums[3];                 // sum_y, sum_exp(-y), sum_zs^2
__device__ int    g_cnt[Qq];
__device__ float  g_t[Qq];
__device__ float  g_x[Qq];                   // rhs r = t/n, then solution
__device__ float  g_A[(size_t)Qq * Qq];      // 16 MB: A, then its Cholesky L (lower), diag blocks later replaced by L_pp^{-1}
__device__ double g_logdiag[NP];

// ---------------- helpers ----------------
__device__ __forceinline__ double block_reduce_d(double v, double* sbuf) {
    int t = threadIdx.x;
    sbuf[t] = v;
    __syncthreads();
    for (int s = blockDim.x >> 1; s > 0; s >>= 1) {
        if (t < s) sbuf[t] += sbuf[t + s];
        __syncthreads();
    }
    double r = sbuf[0];
    __syncthreads();
    return r;
}

// ---------------- kernel 1: per-element transform + scalar sums ----------------
__global__ void k_pre(const float* __restrict__ yt, const float* __restrict__ yp,
                      const float* __restrict__ se, const float* __restrict__ sb) {
    __shared__ double sbuf[1024];
    int tid = threadIdx.x;
    float e = se[0], b = sb[0];
    float sig2 = e + b;
    float inv = 1.0f / ((float)CC * sqrtf(sig2));
    double sy = 0.0, sen = 0.0, sz2 = 0.0;
    for (int i = tid; i < Nn; i += 1024) {
        float y  = (yt[i] - yp[i]) * inv + (float)EULERC;
        float en = expf(-y);
        float u  = expf(-en);
        u = fminf(fmaxf(u, 1e-6f), 1.0f - 1e-6f);
        float zs = 1.41421356237309515f * erfinvf(2.0f * u - 1.0f);
        g_zs[i] = zs;
        sy  += (double)y;
        sen += (double)en;
        sz2 += (double)zs * (double)zs;
    }
    double r;
    r = block_reduce_d(sy, sbuf);  if (tid == 0) g_sums[0] = r;
    r = block_reduce_d(sen, sbuf); if (tid == 0) g_sums[1] = r;
    r = block_reduce_d(sz2, sbuf); if (tid == 0) g_sums[2] = r;
}

// ---------------- kernel 2: deterministic group counts / sums ----------------
__global__ void k_groups(const long long* __restrict__ Z) {
    int q = blockIdx.x * blockDim.x + threadIdx.x;   // 2 x 1024 = Qq threads
    if (q >= Qq) return;
    int c = 0;
    float t = 0.0f;
    for (int i = 0; i < Nn; i++) {
        if ((int)Z[i] == q) { c++; t += g_zs[i]; }
    }
    g_cnt[q] = c;
    g_t[q]   = t;
    g_x[q]   = (c > 0) ? (t / (float)c) : 0.0f;
}

// ---------------- kernel 3: build A = diag(1/n) + D_PP / e (masked, full Q) --------
__global__ void k_buildA(const float* __restrict__ dist, const float* __restrict__ se,
                         const float* __restrict__ sb, const float* __restrict__ ell) {
    float e = se[0], b = sb[0];
    float inv2l = -1.0f / (2.0f * ell[0]);
    float scale = b / e;
    int idx = blockIdx.x * blockDim.x + threadIdx.x;   // exactly Qq*Qq threads
    int q = idx >> 11;
    int r = idx & (Qq - 1);
    int mq = (g_cnt[q] > 0);
    int mr = (g_cnt[r] > 0);
    float v = 0.0f;
    if (mq && mr) v = scale * expf(dist[(size_t)q * LDIM + r] * inv2l);
    if (q == r)  v = mq ? (v + 1.0f / (float)g_cnt[q]) : 1.0f;
    g_A[idx] = v;
}

// ---------------- Cholesky: factor 64x64 diag block ----------------
__global__ void k_potf2(int kb) {
    __shared__ float s[64][65];
    int tid = threadIdx.x;   // 256
    float* Ab = g_A + (size_t)(kb * NB) * Qq + kb * NB;
    for (int i = tid; i < 64 * 64; i += 256)
        s[i >> 6][i & 63] = Ab[(size_t)(i >> 6) * Qq + (i & 63)];
    __syncthreads();
    for (int j = 0; j < 64; j++) {
        if (tid == 0) s[j][j] = sqrtf(s[j][j]);
        __syncthreads();
        float pj = s[j][j];
        for (int i = j + 1 + tid; i < 64; i += 256) s[i][j] /= pj;
        __syncthreads();
        for (int idx = tid; idx < 64 * 64; idx += 256) {
            int i = idx >> 6, c = idx & 63;
            if (i > j && c > j) s[i][c] -= s[i][j] * s[c][j];
        }
        __syncthreads();
    }
    for (int i = tid; i < 64 * 64; i += 256)
        Ab[(size_t)(i >> 6) * Qq + (i & 63)] = s[i >> 6][i & 63];
    if (tid == 0) {
        double acc = 0.0;
        for (int j = 0; j < 64; j++) acc += log((double)s[j][j]);
        g_logdiag[kb] = acc;
    }
}

// ---------------- Cholesky: panel trsm  L21 = A21 * L11^{-T} ----------------
__global__ void k_trsm(int kb) {
    __shared__ float Ld[64][65];
    __shared__ float rd[64];
    int tid = threadIdx.x;   // 256
    const float* Ab = g_A + (size_t)(kb * NB) * Qq + kb * NB;
    for (int i = tid; i < 64 * 64; i += 256)
        Ld[i >> 6][i & 63] = Ab[(size_t)(i >> 6) * Qq + (i & 63)];
    __syncthreads();
    if (tid < 64) rd[tid] = 1.0f / Ld[tid][tid];
    __syncthreads();
    int row = kb * NB + NB + blockIdx.x * blockDim.x + tid;
    if (row >= Qq) return;
    float* a = g_A + (size_t)row * Qq + kb * NB;
    float x[64];
#pragma unroll
    for (int c = 0; c < 64; c++) x[c] = a[c];
#pragma unroll
    for (int c = 0; c < 64; c++) {
        float v = x[c];
#pragma unroll
        for (int p = 0; p < c; p++) v -= x[p] * Ld[c][p];
        x[c] = v * rd[c];
    }
#pragma unroll
    for (int c = 0; c < 64; c++) a[c] = x[c];
}

// ---------------- Cholesky: trailing syrk  A22 -= L21 * L21^T (lower) -------
__global__ void k_syrk(int kb) {
    int nt0 = kb + 1;
    int bx = blockIdx.x + nt0;   // row tile
    int by = blockIdx.y + nt0;   // col tile
    if (by > bx) return;
    __shared__ float Pa[64][65];
    __shared__ float Pb[64][65];
    int tid = threadIdx.x;  // 256
    const float* baseA = g_A + (size_t)(bx * 64) * Qq + kb * NB;
    const float* baseB = g_A + (size_t)(by * 64) * Qq + kb * NB;
    for (int i = tid; i < 64 * 64; i += 256) {
        int r = i >> 6, c = i & 63;
        Pa[r][c] = baseA[(size_t)r * Qq + c];
        Pb[r][c] = baseB[(size_t)r * Qq + c];
    }
    __syncthreads();
    int ty = tid >> 4, tx = tid & 15;   // 16x16 threads, 4x4 micro-tile
    float acc[4][4];
#pragma unroll
    for (int i = 0; i < 4; i++)
#pragma unroll
        for (int j = 0; j < 4; j++) acc[i][j] = 0.0f;
#pragma unroll 8
    for (int k = 0; k < 64; k++) {
        float a0 = Pa[ty * 4 + 0][k], a1 = Pa[ty * 4 + 1][k];
        float a2 = Pa[ty * 4 + 2][k], a3 = Pa[ty * 4 + 3][k];
        float b0 = Pb[tx * 4 + 0][k], b1 = Pb[tx * 4 + 1][k];
        float b2 = Pb[tx * 4 + 2][k], b3 = Pb[tx * 4 + 3][k];
        acc[0][0] += a0 * b0; acc[0][1] += a0 * b1; acc[0][2] += a0 * b2; acc[0][3] += a0 * b3;
        acc[1][0] += a1 * b0; acc[1][1] += a1 * b1; acc[1][2] += a1 * b2; acc[1][3] += a1 * b3;
        acc[2][0] += a2 * b0; acc[2][1] += a2 * b1; acc[2][2] += a2 * b2; acc[2][3] += a2 * b3;
        acc[3][0] += a3 * b0; acc[3][1] += a3 * b1; acc[3][2] += a3 * b2; acc[3][3] += a3 * b3;
    }
    float* C = g_A + (size_t)(bx * 64 + ty * 4) * Qq + by * 64 + tx * 4;
#pragma unroll
    for (int i = 0; i < 4; i++) {
#pragma unroll
        for (int j = 0; j < 4; j++) C[(size_t)i * Qq + j] -= acc[i][j];
    }
}

// ---------------- invert all 64x64 lower-tri diag blocks (for fast solves) --
__global__ void k_invdiag() {
    int kb = blockIdx.x;     // 32 blocks
    int t = threadIdx.x;     // 64 threads, thread t = column t
    __shared__ float Ls[64][65];
    __shared__ float Ws[64][65];
    float* Ab = g_A + (size_t)(kb * NB) * Qq + kb * NB;
    for (int i = 0; i < 64; i++) Ls[i][t] = Ab[(size_t)i * Qq + t];
    __syncthreads();
    for (int i = 0; i < 64; i++) Ws[i][t] = 0.0f;
    Ws[t][t] = 1.0f / Ls[t][t];
    for (int i = t + 1; i < 64; i++) {
        float s = 0.0f;
        for (int c = t; c < i; c++) s += Ls[i][c] * Ws[c][t];
        Ws[i][t] = -s / Ls[i][i];
    }
    __syncthreads();
    for (int i = 0; i < 64; i++) Ab[(size_t)i * Qq + t] = Ws[i][t];
}

// ---------------- single-block: forward+backward solve + final scalar -------
__global__ void k_solve_final(const float* __restrict__ se, const float* __restrict__ sb,
                              float* __restrict__ out) {
    __shared__ float  xs[Qq];        // 8 KB
    __shared__ float  Wd[64][65];    // 16.25 KB
    __shared__ float  tmp[64];
    __shared__ double sbuf[1024];    // 8 KB
    int tid = threadIdx.x;           // 1024

    for (int i = tid; i < Qq; i += 1024) xs[i] = g_x[i];
    __syncthreads();

    // ---- forward solve: L y = r  (diag blocks hold L_pp^{-1}) ----
    for (int p = 0; p < NP; p++) {
        int pb = p * NB;
        const float* Db = g_A + (size_t)pb * Qq + pb;
        for (int i = tid; i < 64 * 64; i += 1024)
            Wd[i >> 6][i & 63] = Db[(size_t)(i >> 6) * Qq + (i & 63)];
        __syncthreads();
        if (tid < 64) {
            float s = 0.0f;
#pragma unroll
            for (int c = 0; c < 64; c++) s += Wd[tid][c] * xs[pb + c];
            tmp[tid] = s;
        }
        __syncthreads();
        if (tid < 64) xs[pb + tid] = tmp[tid];
        __syncthreads();
        for (int r = pb + NB + tid; r < Qq; r += 1024) {
            const float* ar = g_A + (size_t)r * Qq + pb;
            float s = 0.0f;
#pragma unroll
            for (int c = 0; c < 64; c++) s += ar[c] * xs[pb + c];
            xs[r] -= s;
        }
        __syncthreads();
    }

    // ---- backward solve: L^T x = y ----
    for (int p = NP - 1; p >= 0; p--) {
        int pb = p * NB;
        const float* Db = g_A + (size_t)pb * Qq + pb;
        for (int i = tid; i < 64 * 64; i += 1024)
            Wd[i >> 6][i & 63] = Db[(size_t)(i >> 6) * Qq + (i & 63)];
        __syncthreads();
        if (tid < 64) {
            float s = 0.0f;
#pragma unroll
            for (int c = 0; c < 64; c++) s += Wd[c][tid] * xs[pb + c];  // W^T matvec
            tmp[tid] = s;
        }
        __syncthreads();
        if (tid < 64) xs[pb + tid] = tmp[tid];
        __syncthreads();
        for (int c = tid; c < pb; c += 1024) {
            float s = 0.0f;
#pragma unroll
            for (int j = 0; j < 64; j++) s += g_A[(size_t)(pb + j) * Qq + c] * xs[pb + j];
            xs[c] -= s;
        }
        __syncthreads();
    }

    // ---- final reductions and scalar assembly ----
    double s1 = 0.0, slogn = 0.0;
    for (int q = tid; q < Qq; q += 1024) {
        int c = g_cnt[q];
        if (c > 0) {
            double tq = (double)g_t[q];
            s1 += tq * (tq - (double)xs[q]) / (double)c;
            slogn += log((double)c);
        }
    }
    double S1 = block_reduce_d(s1, sbuf);
    double SL = block_reduce_d(slogn, sbuf);
    if (tid == 0) {
        double sumlogL = 0.0;
        for (int i = 0; i < NP; i++) sumlogL += g_logdiag[i];
        double e = (double)se[0], b = (double)sb[0];
        double sig2 = e + b;
        double sy = g_sums[0], sen = g_sums[1], sz2 = g_sums[2];
        double mld = 2.0 * sy + 2.0 * sen + (double)Nn * log(sig2) + (double)Nn * log(C2C);
        double quad = sig2 / e * (sz2 - S1);
        double logdetR = (double)Nn * log(e) + SL + 2.0 * sumlogL - (double)Nn * log(sig2);
        double res = mld + quad - sz2 + logdetR;
        out[0] = (float)res;
    }
}

// ---------------- launch ----------------
extern "C" void kernel_launch(void* const* d_in, const int* in_sizes, int n_in,
                              void* d_out, int out_size) {
    const float*     y_true = (const float*)d_in[0];
    const float*     y_pred = (const float*)d_in[1];
    const float*     sig2e  = (const float*)d_in[2];
    const float*     sig2bs = (const float*)d_in[3];
    const float*     ell    = (const float*)d_in[4];
    const float*     dist   = (const float*)d_in[5];
    const long long* Z_idx  = (const long long*)d_in[6];
    float* out = (float*)d_out;

    k_pre<<<1, 1024>>>(y_true, y_pred, sig2e, sig2bs);
    k_groups<<<2, 1024>>>(Z_idx);
    k_buildA<<<(Qq * Qq) / 1024, 1024>>>(dist, sig2e, sig2bs, ell);

    for (int kb = 0; kb < NP; kb++) {
        k_potf2<<<1, 256>>>(kb);
        int m = NP - 1 - kb;
        if (m > 0) {
            int rows = m * NB;
            k_trsm<<<(rows + 255) / 256, 256>>>(kb);
            dim3 g(m, m);
            k_syrk<<<g, 256>>>(kb);
        }
    }
    k_invdiag<<<NP, 64>>>();
    k_solve_final<<<1, 1024>>>(sig2e, sig2bs, out);
}

// round 3
// speedup vs baseline: 1.9934x; 1.9934x over previous
#include <cuda_runtime.h>
#include <math.h>

// Problem constants
#define Nn   4096
#define Qq   2048
#define LDIM 8192
#define NB   64
#define NP   (Qq/NB)   // 32

#define EULERC 0.5772156649015329
#define CC     0.7796968012336761   // sqrt(6)/pi
#define C2C    0.6079271018540267   // 6/pi^2
#define ZSCALE 16777216.0f          // 2^24 fixed-point scale for deterministic sums

// ---------------- device scratch (static, allocation-free) ----------------
__device__ float  g_zs[Nn];
__device__ double g_sums[3];                 // sum_y, sum_exp(-y), sum_zs^2
__device__ int    g_cnt[Qq];
__device__ unsigned long long g_tsum[Qq];    // fixed-point group sums
__device__ float  g_t[Qq];
__device__ float  g_x[Qq];                   // rhs r = t/n, then solution
__device__ float  g_A[(size_t)Qq * Qq];      // 16 MB
__device__ double g_logdiag[NP];

// ---------------- helpers ----------------
__device__ __forceinline__ double block_reduce_d(double v, double* sbuf) {
    int t = threadIdx.x;
    sbuf[t] = v;
    __syncthreads();
    for (int s = blockDim.x >> 1; s > 0; s >>= 1) {
        if (t < s) sbuf[t] += sbuf[t + s];
        __syncthreads();
    }
    double r = sbuf[0];
    __syncthreads();
    return r;
}

// ---------------- kernel 1: per-element transform + scalar sums ----------------
__global__ void k_pre(const float* __restrict__ yt, const float* __restrict__ yp,
                      const float* __restrict__ se, const float* __restrict__ sb) {
    __shared__ double sbuf[1024];
    int tid = threadIdx.x;
    float e = se[0], b = sb[0];
    float sig2 = e + b;
    float inv = 1.0f / ((float)CC * sqrtf(sig2));
    double sy = 0.0, sen = 0.0, sz2 = 0.0;
    for (int i = tid; i < Nn; i += 1024) {
        float y  = (yt[i] - yp[i]) * inv + (float)EULERC;
        float en = expf(-y);
        float u  = expf(-en);
        u = fminf(fmaxf(u, 1e-6f), 1.0f - 1e-6f);
        float zs = 1.41421356237309515f * erfinvf(2.0f * u - 1.0f);
        g_zs[i] = zs;
        sy  += (double)y;
        sen += (double)en;
        sz2 += (double)zs * (double)zs;
    }
    double r;
    r = block_reduce_d(sy, sbuf);  if (tid == 0) g_sums[0] = r;
    r = block_reduce_d(sen, sbuf); if (tid == 0) g_sums[1] = r;
    r = block_reduce_d(sz2, sbuf); if (tid == 0) g_sums[2] = r;
}

// ---------------- kernel 2: deterministic group histogram (global int atomics) -----
// Single block: zero -> sync -> atomics (global, exact integers) -> sync -> finalize.
// Index masked to [0,Qq) so corrupt data can never fault.
__global__ void k_acc(const long long* __restrict__ Z) {
    int tid = threadIdx.x;                             // 1024
    for (int q = tid; q < Qq; q += 1024) { g_cnt[q] = 0; g_tsum[q] = 0ULL; }
    __syncthreads();
    for (int i = tid; i < Nn; i += 1024) {
        int q = ((int)Z[i]) & (Qq - 1);
        long long fx = (long long)llrintf(g_zs[i] * ZSCALE);
        atomicAdd(&g_cnt[q], 1);
        atomicAdd(&g_tsum[q], (unsigned long long)fx);
    }
    __syncthreads();
    for (int q = tid; q < Qq; q += 1024) {
        int c = g_cnt[q];
        float t = (float)((double)(long long)g_tsum[q] / (double)ZSCALE);
        g_t[q] = t;
        g_x[q] = (c > 0) ? (t / (float)c) : 0.0f;
    }
}

// ---------------- kernel 3: build A = diag(1/n) + D_PP / e (masked, full Q) --------
__global__ void k_buildA(const float* __restrict__ dist, const float* __restrict__ se,
                         const float* __restrict__ sb, const float* __restrict__ ell) {
    float e = se[0], b = sb[0];
    float inv2l = -1.0f / (2.0f * ell[0]);
    float scale = b / e;
    int idx = blockIdx.x * blockDim.x + threadIdx.x;   // exactly Qq*Qq threads
    int q = idx >> 11;
    int r = idx & (Qq - 1);
    int mq = (g_cnt[q] > 0);
    int mr = (g_cnt[r] > 0);
    float v = 0.0f;
    if (mq && mr) v = scale * expf(dist[(size_t)q * LDIM + r] * inv2l);
    if (q == r)  v = mq ? (v + 1.0f / (float)g_cnt[q]) : 1.0f;
    g_A[idx] = v;
}

// ---------------- Cholesky: factor 64x64 diag block (register-column version) ------
// 256 threads: tcol = t & 63 owns column tcol, trow = t >> 6 owns 16 rows of it.
__global__ void k_potf2(int kb) {
    int t = threadIdx.x;           // 256
    int tcol = t & 63;
    int trow = t >> 6;             // 0..3
    int rbase = trow * 16;
    float* Ab = g_A + (size_t)(kb * NB) * Qq + kb * NB;
    float c[16];
#pragma unroll
    for (int i = 0; i < 16; i++)
        c[i] = Ab[(size_t)(rbase + i) * Qq + tcol];   // coalesced across tcol
    __shared__ float bc[64];
    double logacc = 0.0;
    for (int j = 0; j < 64; j++) {
        // owners of column j broadcast the RAW (current) column
        if (tcol == j) {
#pragma unroll
            for (int i = 0; i < 16; i++) bc[rbase + i] = c[i];
        }
        __syncthreads();
        float d = sqrtf(bc[j]);    // every thread computes (parallel, deterministic)
        float r = 1.0f / d;
        if (t == 0) logacc += (double)logf(d);
        if (tcol == j) {
            // scale own column: L[i][j] = raw[i] / d   (i >= j)
#pragma unroll
            for (int i = 0; i < 16; i++) {
                int gi = rbase + i;
                if (gi >= j) c[i] = bc[gi] * r;
            }
        } else if (tcol > j) {
            // A[:,tcol] -= L[tcol][j] * L[:,j]  == (bc[tcol]*r) * (bc[i]*r)
            float fr = bc[tcol] * (r * r);
#pragma unroll
            for (int i = 0; i < 16; i++) {
                int gi = rbase + i;
                if (gi > j) c[i] -= fr * bc[gi];
            }
        }
        __syncthreads();
    }
#pragma unroll
    for (int i = 0; i < 16; i++)
        Ab[(size_t)(rbase + i) * Qq + tcol] = c[i];
    if (t == 0) g_logdiag[kb] = logacc;
}

// ---------------- Cholesky: panel trsm  L21 = A21 * L11^{-T} ----------------
__global__ void k_trsm(int kb) {
    __shared__ float Ld[64][65];
    __shared__ float rd[64];
    int tid = threadIdx.x;   // 256
    const float* Ab = g_A + (size_t)(kb * NB) * Qq + kb * NB;
    for (int i = tid; i < 64 * 64; i += 256)
        Ld[i >> 6][i & 63] = Ab[(size_t)(i >> 6) * Qq + (i & 63)];
    __syncthreads();
    if (tid < 64) rd[tid] = 1.0f / Ld[tid][tid];
    __syncthreads();
    int row = kb * NB + NB + blockIdx.x * blockDim.x + tid;
    if (row >= Qq) return;
    float* a = g_A + (size_t)row * Qq + kb * NB;
    float x[64];
#pragma unroll
    for (int c = 0; c < 64; c++) x[c] = a[c];
#pragma unroll
    for (int c = 0; c < 64; c++) {
        float v = x[c];
#pragma unroll
        for (int p = 0; p < c; p++) v -= x[p] * Ld[c][p];
        x[c] = v * rd[c];
    }
#pragma unroll
    for (int c = 0; c < 64; c++) a[c] = x[c];
}

// ---------------- Cholesky: trailing syrk  A22 -= L21 * L21^T (lower) -------
__global__ void k_syrk(int kb) {
    int nt0 = kb + 1;
    int bx = blockIdx.x + nt0;   // row tile
    int by = blockIdx.y + nt0;   // col tile
    if (by > bx) return;
    __shared__ float Pa[64][65];
    __shared__ float Pb[64][65];
    int tid = threadIdx.x;  // 256
    const float* baseA = g_A + (size_t)(bx * 64) * Qq + kb * NB;
    const float* baseB = g_A + (size_t)(by * 64) * Qq + kb * NB;
    for (int i = tid; i < 64 * 64; i += 256) {
        int r = i >> 6, c = i & 63;
        Pa[r][c] = baseA[(size_t)r * Qq + c];
        Pb[r][c] = baseB[(size_t)r * Qq + c];
    }
    __syncthreads();
    int ty = tid >> 4, tx = tid & 15;   // 16x16 threads, 4x4 micro-tile
    float acc[4][4];
#pragma unroll
    for (int i = 0; i < 4; i++)
#pragma unroll
        for (int j = 0; j < 4; j++) acc[i][j] = 0.0f;
#pragma unroll 8
    for (int k = 0; k < 64; k++) {
        float a0 = Pa[ty * 4 + 0][k], a1 = Pa[ty * 4 + 1][k];
        float a2 = Pa[ty * 4 + 2][k], a3 = Pa[ty * 4 + 3][k];
        float b0 = Pb[tx * 4 + 0][k], b1 = Pb[tx * 4 + 1][k];
        float b2 = Pb[tx * 4 + 2][k], b3 = Pb[tx * 4 + 3][k];
        acc[0][0] += a0 * b0; acc[0][1] += a0 * b1; acc[0][2] += a0 * b2; acc[0][3] += a0 * b3;
        acc[1][0] += a1 * b0; acc[1][1] += a1 * b1; acc[1][2] += a1 * b2; acc[1][3] += a1 * b3;
        acc[2][0] += a2 * b0; acc[2][1] += a2 * b1; acc[2][2] += a2 * b2; acc[2][3] += a2 * b3;
        acc[3][0] += a3 * b0; acc[3][1] += a3 * b1; acc[3][2] += a3 * b2; acc[3][3] += a3 * b3;
    }
    float* C = g_A + (size_t)(bx * 64 + ty * 4) * Qq + by * 64 + tx * 4;
#pragma unroll
    for (int i = 0; i < 4; i++) {
#pragma unroll
        for (int j = 0; j < 4; j++) C[(size_t)i * Qq + j] -= acc[i][j];
    }
}

// ---------------- invert all 64x64 lower-tri diag blocks (for fast solves) --
__global__ void k_invdiag() {
    int kb = blockIdx.x;     // 32 blocks
    int t = threadIdx.x;     // 64 threads, thread t = column t
    __shared__ float Ls[64][65];
    __shared__ float Ws[64][65];
    float* Ab = g_A + (size_t)(kb * NB) * Qq + kb * NB;
    for (int i = 0; i < 64; i++) Ls[i][t] = Ab[(size_t)i * Qq + t];
    __syncthreads();
    for (int i = 0; i < 64; i++) Ws[i][t] = 0.0f;
    Ws[t][t] = 1.0f / Ls[t][t];
    for (int i = t + 1; i < 64; i++) {
        float s = 0.0f;
        for (int c = t; c < i; c++) s += Ls[i][c] * Ws[c][t];
        Ws[i][t] = -s / Ls[i][i];
    }
    __syncthreads();
    for (int i = 0; i < 64; i++) Ab[(size_t)i * Qq + t] = Ws[i][t];
}

// ---------------- single-block: forward+backward solve + final scalar -------
__global__ void k_solve_final(const float* __restrict__ se, const float* __restrict__ sb,
                              float* __restrict__ out) {
    __shared__ float  xs[Qq];        // 8 KB
    __shared__ float  Wd[64][65];    // 16.25 KB
    __shared__ float  tmp[64];
    __shared__ double sbuf[1024];    // 8 KB
    int tid = threadIdx.x;           // 1024

    for (int i = tid; i < Qq; i += 1024) xs[i] = g_x[i];
    __syncthreads();

    // ---- forward solve: L y = r  (diag blocks hold L_pp^{-1}) ----
    for (int p = 0; p < NP; p++) {
        int pb = p * NB;
        const float* Db = g_A + (size_t)pb * Qq + pb;
        for (int i = tid; i < 64 * 64; i += 1024)
            Wd[i >> 6][i & 63] = Db[(size_t)(i >> 6) * Qq + (i & 63)];
        __syncthreads();
        if (tid < 64) {
            float s = 0.0f;
#pragma unroll
            for (int c = 0; c < 64; c++) s += Wd[tid][c] * xs[pb + c];
            tmp[tid] = s;
        }
        __syncthreads();
        if (tid < 64) xs[pb + tid] = tmp[tid];
        __syncthreads();
        for (int r = pb + NB + tid; r < Qq; r += 1024) {
            const float* ar = g_A + (size_t)r * Qq + pb;
            float s = 0.0f;
#pragma unroll
            for (int c = 0; c < 64; c++) s += ar[c] * xs[pb + c];
            xs[r] -= s;
        }
        __syncthreads();
    }

    // ---- backward solve: L^T x = y ----
    for (int p = NP - 1; p >= 0; p--) {
        int pb = p * NB;
        const float* Db = g_A + (size_t)pb * Qq + pb;
        for (int i = tid; i < 64 * 64; i += 1024)
            Wd[i >> 6][i & 63] = Db[(size_t)(i >> 6) * Qq + (i & 63)];
        __syncthreads();
        if (tid < 64) {
            float s = 0.0f;
#pragma unroll
            for (int c = 0; c < 64; c++) s += Wd[c][tid] * xs[pb + c];  // W^T matvec
            tmp[tid] = s;
        }
        __syncthreads();
        if (tid < 64) xs[pb + tid] = tmp[tid];
        __syncthreads();
        for (int c = tid; c < pb; c += 1024) {
            float s = 0.0f;
#pragma unroll
            for (int j = 0; j < 64; j++) s += g_A[(size_t)(pb + j) * Qq + c] * xs[pb + j];
            xs[c] -= s;
        }
        __syncthreads();
    }

    // ---- final reductions and scalar assembly ----
    double s1 = 0.0, slogn = 0.0;
    for (int q = tid; q < Qq; q += 1024) {
        int c = g_cnt[q];
        if (c > 0) {
            double tq = (double)g_t[q];
            s1 += tq * (tq - (double)xs[q]) / (double)c;
            slogn += log((double)c);
        }
    }
    double S1 = block_reduce_d(s1, sbuf);
    double SL = block_reduce_d(slogn, sbuf);
    if (tid == 0) {
        double sumlogL = 0.0;
        for (int i = 0; i < NP; i++) sumlogL += g_logdiag[i];
        double e = (double)se[0], b = (double)sb[0];
        double sig2 = e + b;
        double sy = g_sums[0], sen = g_sums[1], sz2 = g_sums[2];
        double mld = 2.0 * sy + 2.0 * sen + (double)Nn * log(sig2) + (double)Nn * log(C2C);
        double quad = sig2 / e * (sz2 - S1);
        double logdetR = (double)Nn * log(e) + SL + 2.0 * sumlogL - (double)Nn * log(sig2);
        double res = mld + quad - sz2 + logdetR;
        out[0] = (float)res;
    }
}

// ---------------- launch ----------------
extern "C" void kernel_launch(void* const* d_in, const int* in_sizes, int n_in,
                              void* d_out, int out_size) {
    const float*     y_true = (const float*)d_in[0];
    const float*     y_pred = (const float*)d_in[1];
    const float*     sig2e  = (const float*)d_in[2];
    const float*     sig2bs = (const float*)d_in[3];
    const float*     ell    = (const float*)d_in[4];
    const float*     dist   = (const float*)d_in[5];
    const long long* Z_idx  = (const long long*)d_in[6];
    float* out = (float*)d_out;

    k_pre<<<1, 1024>>>(y_true, y_pred, sig2e, sig2bs);
    k_acc<<<1, 1024>>>(Z_idx);
    k_buildA<<<(Qq * Qq) / 1024, 1024>>>(dist, sig2e, sig2bs, ell);

    for (int kb = 0; kb < NP; kb++) {
        k_potf2<<<1, 256>>>(kb);
        int m = NP - 1 - kb;
        if (m > 0) {
            int rows = m * NB;
            k_trsm<<<(rows + 255) / 256, 256>>>(kb);
            dim3 g(m, m);
            k_syrk<<<g, 256>>>(kb);
        }
    }
    k_invdiag<<<NP, 64>>>();
    k_solve_final<<<1, 1024>>>(sig2e, sig2bs, out);
}

// round 4
// speedup vs baseline: 3.9276x; 1.9703x over previous
#include <cuda_runtime.h>
#include <math.h>

// Problem constants
#define Nn   4096
#define Qq   2048
#define LDIM 8192
#define NB   64
#define NP   (Qq/NB)   // 32

#define EULERC 0.5772156649015329
#define CC     0.7796968012336761   // sqrt(6)/pi
#define C2C    0.6079271018540267   // 6/pi^2
#define ZSCALE 16777216.0f          // 2^24 fixed-point scale for deterministic sums

// ---------------- device scratch (static, allocation-free) ----------------
__device__ float  g_zs[Nn];
__device__ double g_sums[3];                 // sum_y, sum_exp(-y), sum_zs^2
__device__ int    g_cnt[Qq];
__device__ unsigned long long g_tsum[Qq];    // fixed-point group sums
__device__ float  g_t[Qq];
__device__ float  g_x[Qq];                   // rhs r = t/n
// (Qq+1) rows x Qq cols: row Qq holds the rhs r, becomes y = L^{-1} r after sweep
__device__ float  g_A[(size_t)(Qq + 1) * Qq];
__device__ double g_logdiag[NP];

// ---------------- helpers ----------------
__device__ __forceinline__ double block_reduce_d(double v, double* sbuf) {
    int t = threadIdx.x;
    sbuf[t] = v;
    __syncthreads();
    for (int s = blockDim.x >> 1; s > 0; s >>= 1) {
        if (t < s) sbuf[t] += sbuf[t + s];
        __syncthreads();
    }
    double r = sbuf[0];
    __syncthreads();
    return r;
}

// 64x64 Cholesky of tile in shared S (row-major [64][65]), result written to
// gout (leading dim Qq). One bar per column via double-buffered broadcast.
// 256 threads: tcol = t&63 owns column tcol, trow = t>>6 owns 16 rows.
__device__ void potf2_core(float S[64][65], float buf[2][64],
                           float* gout, int logidx) {
    int t = threadIdx.x;
    int tcol = t & 63;
    int rbase = (t >> 6) * 16;
    float c[16];
#pragma unroll
    for (int i = 0; i < 16; i++) c[i] = S[rbase + i][tcol];
    if (tcol == 0) {
#pragma unroll
        for (int i = 0; i < 16; i++) buf[0][rbase + i] = c[i];
    }
    __syncthreads();
    double logacc = 0.0;
    for (int j = 0; j < 64; j++) {
        float* bc = buf[j & 1];
        float pj = bc[j];
        float r = rsqrtf(pj);
        if (t == 0) logacc += 0.5 * (double)logf(pj);
        if (tcol == j) {
#pragma unroll
            for (int i = 0; i < 16; i++) {
                int gi = rbase + i;
                if (gi >= j) c[i] = bc[gi] * r;
            }
        } else if (tcol > j) {
            float fr = bc[tcol] * (r * r);
#pragma unroll
            for (int i = 0; i < 16; i++) {
                int gi = rbase + i;
                if (gi > j) c[i] -= fr * bc[gi];
            }
            if (tcol == j + 1) {
#pragma unroll
                for (int i = 0; i < 16; i++) buf[(j + 1) & 1][rbase + i] = c[i];
            }
        }
        __syncthreads();
    }
#pragma unroll
    for (int i = 0; i < 16; i++)
        gout[(size_t)(rbase + i) * Qq + tcol] = c[i];
    if (t == 0) g_logdiag[logidx] = logacc;
}

// ---------------- kernel 1: per-element transform + scalar sums ----------------
__global__ void k_pre(const float* __restrict__ yt, const float* __restrict__ yp,
                      const float* __restrict__ se, const float* __restrict__ sb) {
    __shared__ double sbuf[1024];
    int tid = threadIdx.x;
    float e = se[0], b = sb[0];
    float sig2 = e + b;
    float inv = 1.0f / ((float)CC * sqrtf(sig2));
    double sy = 0.0, sen = 0.0, sz2 = 0.0;
    for (int i = tid; i < Nn; i += 1024) {
        float y  = (yt[i] - yp[i]) * inv + (float)EULERC;
        float en = expf(-y);
        float u  = expf(-en);
        u = fminf(fmaxf(u, 1e-6f), 1.0f - 1e-6f);
        float zs = 1.41421356237309515f * erfinvf(2.0f * u - 1.0f);
        g_zs[i] = zs;
        sy  += (double)y;
        sen += (double)en;
        sz2 += (double)zs * (double)zs;
    }
    double r;
    r = block_reduce_d(sy, sbuf);  if (tid == 0) g_sums[0] = r;
    r = block_reduce_d(sen, sbuf); if (tid == 0) g_sums[1] = r;
    r = block_reduce_d(sz2, sbuf); if (tid == 0) g_sums[2] = r;
}

// ---------------- kernel 2: deterministic group histogram (global int atomics) -----
__global__ void k_acc(const long long* __restrict__ Z) {
    int tid = threadIdx.x;                             // 1024
    for (int q = tid; q < Qq; q += 1024) { g_cnt[q] = 0; g_tsum[q] = 0ULL; }
    __syncthreads();
    for (int i = tid; i < Nn; i += 1024) {
        int q = ((int)Z[i]) & (Qq - 1);
        long long fx = (long long)llrintf(g_zs[i] * ZSCALE);
        atomicAdd(&g_cnt[q], 1);
        atomicAdd(&g_tsum[q], (unsigned long long)fx);
    }
    __syncthreads();
    for (int q = tid; q < Qq; q += 1024) {
        int c = g_cnt[q];
        float t = (float)((double)(long long)g_tsum[q] / (double)ZSCALE);
        g_t[q] = t;
        g_x[q] = (c > 0) ? (t / (float)c) : 0.0f;
    }
}

// ---------------- kernel 3: build A = diag(1/n) + D_PP/e, plus rhs row Qq ----------
__global__ void k_buildA(const float* __restrict__ dist, const float* __restrict__ se,
                         const float* __restrict__ sb, const float* __restrict__ ell) {
    int idx = blockIdx.x * blockDim.x + threadIdx.x;
    if (idx >= (Qq + 1) * Qq) return;
    int q = idx >> 11;
    int r = idx & (Qq - 1);
    if (q == Qq) {                 // bordered rhs row: r vector
        g_A[idx] = g_x[r];
        return;
    }
    float e = se[0], b = sb[0];
    float inv2l = -1.0f / (2.0f * ell[0]);
    float scale = b / e;
    int mq = (g_cnt[q] > 0);
    int mr = (g_cnt[r] > 0);
    float v = 0.0f;
    if (mq && mr) v = scale * expf(dist[(size_t)q * LDIM + r] * inv2l);
    if (q == r)  v = mq ? (v + 1.0f / (float)g_cnt[q]) : 1.0f;
    g_A[idx] = v;
}

// ---------------- standalone potf2 for the first diagonal tile -------------
__global__ void k_potf2_first() {
    __shared__ float S[64][65];
    __shared__ float buf[2][64];
    int tid = threadIdx.x;   // 256
    for (int i = tid; i < 64 * 64; i += 256)
        S[i >> 6][i & 63] = g_A[(size_t)(i >> 6) * Qq + (i & 63)];
    __syncthreads();
    potf2_core(S, buf, g_A, 0);
}

// ---------------- panel trsm: rows kb*64+64 .. Qq (incl. rhs row) -----------
// Staged through shared for coalesced global access. 256 rows / block.
__global__ void k_trsm(int kb) {
    __shared__ float Ld[64][65];
    __shared__ float stage[64][65];
    __shared__ float rd[64];
    int tid = threadIdx.x;   // 256
    const float* Ab = g_A + (size_t)(kb * NB) * Qq + kb * NB;
    for (int i = tid; i < 64 * 64; i += 256)
        Ld[i >> 6][i & 63] = Ab[(size_t)(i >> 6) * Qq + (i & 63)];
    __syncthreads();
    if (tid < 64) rd[tid] = 1.0f / Ld[tid][tid];

    int row0 = kb * NB + NB + blockIdx.x * 256;
    float x[64];
    // staged coalesced load: 4 chunks of 64 rows
    for (int ch = 0; ch < 4; ch++) {
        int rb = row0 + ch * 64;
        __syncthreads();
        for (int i = tid; i < 64 * 64; i += 256) {
            int rr = i >> 6, cc = i & 63;
            int grow = rb + rr;
            stage[rr][cc] = (grow <= Qq)
                ? g_A[(size_t)grow * Qq + kb * NB + cc] : 0.0f;
        }
        __syncthreads();
        if ((tid >> 6) == ch) {
            int rr = tid & 63;
#pragma unroll
            for (int c = 0; c < 64; c++) x[c] = stage[rr][c];
        }
    }
    __syncthreads();
    // forward substitution against L11^T (per-row, registers)
#pragma unroll
    for (int c = 0; c < 64; c++) {
        float v = x[c];
#pragma unroll
        for (int p = 0; p < c; p++) v -= x[p] * Ld[c][p];
        x[c] = v * rd[c];
    }
    // staged coalesced store
    for (int ch = 0; ch < 4; ch++) {
        if ((tid >> 6) == ch) {
            int rr = tid & 63;
#pragma unroll
            for (int c = 0; c < 64; c++) stage[rr][c] = x[c];
        }
        __syncthreads();
        int rb = row0 + ch * 64;
        for (int i = tid; i < 64 * 64; i += 256) {
            int rr = i >> 6, cc = i & 63;
            int grow = rb + rr;
            if (grow <= Qq)
                g_A[(size_t)grow * Qq + kb * NB + cc] = stage[rr][cc];
        }
        __syncthreads();
    }
}

// ---------------- trailing syrk, fused with potf2 of next diagonal tile -----
// bx in [kb+1 .. NP] (bx==NP is the rhs-row tile), by in [kb+1 .. NP-1].
__global__ void k_syrk(int kb) {
    int nt0 = kb + 1;
    int bx = blockIdx.x + nt0;
    int by = blockIdx.y + nt0;
    if (by > bx) return;
    bool special = (bx == nt0) && (by == nt0);
    __shared__ float Pa[64][65];
    __shared__ float Pb[64][65];
    __shared__ float bcbuf[2][64];
    int tid = threadIdx.x;  // 256

    const float* baseA = g_A + (size_t)(bx * 64) * Qq + (size_t)kb * NB;
    for (int i = tid; i < 64 * 64; i += 256) {
        int r = i >> 6, c = i & 63;
        int grow = bx * 64 + r;
        Pa[r][c] = (grow <= Qq) ? baseA[(size_t)r * Qq + c] : 0.0f;
    }
    if (special) {
        // Pb holds the current diagonal tile values (to be updated + factored)
        const float* Cd = g_A + (size_t)(bx * 64) * Qq + (size_t)by * 64;
        for (int i = tid; i < 64 * 64; i += 256) {
            int r = i >> 6, c = i & 63;
            Pb[r][c] = Cd[(size_t)r * Qq + c];
        }
    } else {
        const float* baseB = g_A + (size_t)(by * 64) * Qq + (size_t)kb * NB;
        for (int i = tid; i < 64 * 64; i += 256) {
            int r = i >> 6, c = i & 63;
            Pb[r][c] = baseB[(size_t)r * Qq + c];
        }
    }
    __syncthreads();

    int ty = tid >> 4, tx = tid & 15;   // 16x16 threads, 4x4 micro-tile
    float (*Bs)[65] = special ? Pa : Pb;
    float acc[4][4];
#pragma unroll
    for (int i = 0; i < 4; i++)
#pragma unroll
        for (int j = 0; j < 4; j++) acc[i][j] = 0.0f;
#pragma unroll 8
    for (int k = 0; k < 64; k++) {
        float a0 = Pa[ty * 4 + 0][k], a1 = Pa[ty * 4 + 1][k];
        float a2 = Pa[ty * 4 + 2][k], a3 = Pa[ty * 4 + 3][k];
        float b0 = Bs[tx * 4 + 0][k], b1 = Bs[tx * 4 + 1][k];
        float b2 = Bs[tx * 4 + 2][k], b3 = Bs[tx * 4 + 3][k];
        acc[0][0] += a0 * b0; acc[0][1] += a0 * b1; acc[0][2] += a0 * b2; acc[0][3] += a0 * b3;
        acc[1][0] += a1 * b0; acc[1][1] += a1 * b1; acc[1][2] += a1 * b2; acc[1][3] += a1 * b3;
        acc[2][0] += a2 * b0; acc[2][1] += a2 * b1; acc[2][2] += a2 * b2; acc[2][3] += a2 * b3;
        acc[3][0] += a3 * b0; acc[3][1] += a3 * b1; acc[3][2] += a3 * b2; acc[3][3] += a3 * b3;
    }

    if (special) {
        // apply trailing update into shared, then factor the tile in-place
#pragma unroll
        for (int i = 0; i < 4; i++)
#pragma unroll
            for (int j = 0; j < 4; j++) Pb[ty * 4 + i][tx * 4 + j] -= acc[i][j];
        __syncthreads();
        potf2_core(Pb, bcbuf,
                   g_A + (size_t)(nt0 * NB) * Qq + nt0 * NB, nt0);
    } else {
        float* C = g_A + (size_t)(bx * 64 + ty * 4) * Qq + (size_t)by * 64 + tx * 4;
#pragma unroll
        for (int i = 0; i < 4; i++) {
            if (bx * 64 + ty * 4 + i <= Qq) {
#pragma unroll
                for (int j = 0; j < 4; j++) C[(size_t)i * Qq + j] -= acc[i][j];
            }
        }
    }
}

// ---------------- final: ||y||^2 + scalar assembly ----------------
__global__ void k_final(const float* __restrict__ se, const float* __restrict__ sb,
                        float* __restrict__ out) {
    __shared__ double sbuf[256];
    int tid = threadIdx.x;  // 256
    double sy2 = 0.0, st2n = 0.0, slogn = 0.0;
    const float* yrow = g_A + (size_t)Qq * Qq;
    for (int q = tid; q < Qq; q += 256) {
        float y = yrow[q];
        sy2 += (double)y * (double)y;
        int c = g_cnt[q];
        if (c > 0) {
            double tq = (double)g_t[q];
            st2n  += tq * tq / (double)c;
            slogn += log((double)c);
        }
    }
    double SY2 = block_reduce_d(sy2, sbuf);
    double ST  = block_reduce_d(st2n, sbuf);
    double SL  = block_reduce_d(slogn, sbuf);
    if (tid == 0) {
        double sumlogL = 0.0;
        for (int i = 0; i < NP; i++) sumlogL += g_logdiag[i];
        double e = (double)se[0], b = (double)sb[0];
        double sig2 = e + b;
        double sy = g_sums[0], sen = g_sums[1], sz2 = g_sums[2];
        double S1 = ST - SY2;
        double mld = 2.0 * sy + 2.0 * sen + (double)Nn * log(sig2) + (double)Nn * log(C2C);
        double quad = sig2 / e * (sz2 - S1);
        double logdetR = (double)Nn * log(e) + SL + 2.0 * sumlogL - (double)Nn * log(sig2);
        double res = mld + quad - sz2 + logdetR;
        out[0] = (float)res;
    }
}

// ---------------- launch ----------------
extern "C" void kernel_launch(void* const* d_in, const int* in_sizes, int n_in,
                              void* d_out, int out_size) {
    const float*     y_true = (const float*)d_in[0];
    const float*     y_pred = (const float*)d_in[1];
    const float*     sig2e  = (const float*)d_in[2];
    const float*     sig2bs = (const float*)d_in[3];
    const float*     ell    = (const float*)d_in[4];
    const float*     dist   = (const float*)d_in[5];
    const long long* Z_idx  = (const long long*)d_in[6];
    float* out = (float*)d_out;

    k_pre<<<1, 1024>>>(y_true, y_pred, sig2e, sig2bs);
    k_acc<<<1, 1024>>>(Z_idx);
    int nbuild = ((Qq + 1) * Qq + 1023) / 1024;
    k_buildA<<<nbuild, 1024>>>(dist, sig2e, sig2bs, ell);

    k_potf2_first<<<1, 256>>>();
    for (int kb = 0; kb < NP; kb++) {
        int m = NP - 1 - kb;
        int rows = m * 64 + 1;                 // panel rows + rhs row
        k_trsm<<<(rows + 255) / 256, 256>>>(kb);
        if (m > 0) {
            dim3 g(m + 1, m);                  // bx: m panel tiles + rhs tile
            k_syrk<<<g, 256>>>(kb);            // fused: factors diag tile kb+1
        }
    }
    k_final<<<1, 256>>>(sig2e, sig2bs, out);
}

// round 5
// speedup vs baseline: 4.7303x; 1.2044x over previous
#include <cuda_runtime.h>
#include <math.h>

// Problem constants
#define Nn   4096
#define Qq   2048
#define LDIM 8192
#define NB   64
#define NP   (Qq/NB)   // 32

#define EULERC 0.5772156649015329
#define CC     0.7796968012336761   // sqrt(6)/pi
#define C2C    0.6079271018540267   // 6/pi^2
#define ZSCALE 16777216.0f          // 2^24 fixed-point scale for deterministic sums

// ---------------- device scratch (static, allocation-free) ----------------
__device__ float  g_zs[Nn];
__device__ double g_sums[3];                 // sum_y, sum_exp(-y), sum_zs^2
__device__ int    g_cnt[Qq];
__device__ unsigned long long g_tsum[Qq];    // fixed-point group sums
__device__ float  g_t[Qq];
__device__ float  g_x[Qq];                   // rhs r = t/n
// (Qq+1) rows x Qq cols: row Qq holds the rhs r, becomes y = L^{-1} r after sweep
__device__ float  g_A[(size_t)(Qq + 1) * Qq];
__device__ double g_logdiag[NP];

// ---------------- helpers ----------------
__device__ __forceinline__ double block_reduce_d(double v, double* sbuf) {
    int t = threadIdx.x;
    sbuf[t] = v;
    __syncthreads();
    for (int s = blockDim.x >> 1; s > 0; s >>= 1) {
        if (t < s) sbuf[t] += sbuf[t + s];
        __syncthreads();
    }
    double r = sbuf[0];
    __syncthreads();
    return r;
}

// 64x64 Cholesky of tile in shared S (row-major [64][65]); L written to gout
// (leading dim Qq; upper triangle of output is garbage by design).
// Raw-column variant: no in-loop scaling, no predicates, pivot log after loop.
// 256 threads: tcol = t&63 owns column tcol, trow = t>>6 owns 16 rows.
__device__ void potf2_core(float S[64][65], float buf[2][64], float* ds,
                           float* gout, int logidx) {
    int t = threadIdx.x;
    int tcol = t & 63;
    int rbase = (t >> 6) * 16;
    float c[16];
#pragma unroll
    for (int i = 0; i < 16; i++) c[i] = S[rbase + i][tcol];
    if (tcol == 0) {
#pragma unroll
        for (int i = 0; i < 16; i++) buf[0][rbase + i] = c[i];
    }
    __syncthreads();
    for (int j = 0; j < 64; j++) {
        float* bc = buf[j & 1];
        if (t == 0) ds[j] = bc[j];
        if (tcol > j) {
            float fr = bc[tcol] * __frcp_rn(bc[j]);
#pragma unroll
            for (int i = 0; i < 16; i++) c[i] -= fr * bc[rbase + i];
            if (tcol == j + 1) {
#pragma unroll
                for (int i = 0; i < 16; i++) buf[(j + 1) & 1][rbase + i] = c[i];
            }
        }
        __syncthreads();
    }
    // scale raw columns by 1/sqrt(pivot) and store (upper triangle = garbage)
    float r = rsqrtf(ds[tcol]);
#pragma unroll
    for (int i = 0; i < 16; i++)
        gout[(size_t)(rbase + i) * Qq + tcol] = c[i] * r;
    // parallel logdet of this tile: 0.5 * sum_j log(ds[j])
    if (t < 64) {
        float lg = logf(ds[tcol]);
#pragma unroll
        for (int off = 16; off > 0; off >>= 1)
            lg += __shfl_down_sync(0xffffffffu, lg, off);
        if ((t & 31) == 0) buf[1][t >> 5] = lg;
    }
    __syncthreads();
    if (t == 0)
        g_logdiag[logidx] = 0.5 * ((double)buf[1][0] + (double)buf[1][1]);
}

// ---------------- kernel 1: per-element transform + scalar sums ----------------
__global__ void k_pre(const float* __restrict__ yt, const float* __restrict__ yp,
                      const float* __restrict__ se, const float* __restrict__ sb) {
    __shared__ double sbuf[1024];
    int tid = threadIdx.x;
    float e = se[0], b = sb[0];
    float sig2 = e + b;
    float inv = 1.0f / ((float)CC * sqrtf(sig2));
    double sy = 0.0, sen = 0.0, sz2 = 0.0;
    for (int i = tid; i < Nn; i += 1024) {
        float y  = (yt[i] - yp[i]) * inv + (float)EULERC;
        float en = expf(-y);
        float u  = expf(-en);
        u = fminf(fmaxf(u, 1e-6f), 1.0f - 1e-6f);
        float zs = 1.41421356237309515f * erfinvf(2.0f * u - 1.0f);
        g_zs[i] = zs;
        sy  += (double)y;
        sen += (double)en;
        sz2 += (double)zs * (double)zs;
    }
    double r;
    r = block_reduce_d(sy, sbuf);  if (tid == 0) g_sums[0] = r;
    r = block_reduce_d(sen, sbuf); if (tid == 0) g_sums[1] = r;
    r = block_reduce_d(sz2, sbuf); if (tid == 0) g_sums[2] = r;
}

// ---------------- kernel 2: deterministic group histogram (global int atomics) -----
__global__ void k_acc(const long long* __restrict__ Z) {
    int tid = threadIdx.x;                             // 1024
    for (int q = tid; q < Qq; q += 1024) { g_cnt[q] = 0; g_tsum[q] = 0ULL; }
    __syncthreads();
    for (int i = tid; i < Nn; i += 1024) {
        int q = ((int)Z[i]) & (Qq - 1);
        long long fx = (long long)llrintf(g_zs[i] * ZSCALE);
        atomicAdd(&g_cnt[q], 1);
        atomicAdd(&g_tsum[q], (unsigned long long)fx);
    }
    __syncthreads();
    for (int q = tid; q < Qq; q += 1024) {
        int c = g_cnt[q];
        float t = (float)((double)(long long)g_tsum[q] / (double)ZSCALE);
        g_t[q] = t;
        g_x[q] = (c > 0) ? (t / (float)c) : 0.0f;
    }
}

// ---------------- kernel 3: build A = diag(1/n) + D_PP/e, plus rhs row Qq ----------
__global__ void k_buildA(const float* __restrict__ dist, const float* __restrict__ se,
                         const float* __restrict__ sb, const float* __restrict__ ell) {
    int idx = blockIdx.x * blockDim.x + threadIdx.x;
    if (idx >= (Qq + 1) * Qq) return;
    int q = idx >> 11;
    int r = idx & (Qq - 1);
    if (q == Qq) {                 // bordered rhs row: r vector
        g_A[idx] = g_x[r];
        return;
    }
    float e = se[0], b = sb[0];
    float inv2l = -1.0f / (2.0f * ell[0]);
    float scale = b / e;
    int mq = (g_cnt[q] > 0);
    int mr = (g_cnt[r] > 0);
    float v = 0.0f;
    if (mq && mr) v = scale * expf(dist[(size_t)q * LDIM + r] * inv2l);
    if (q == r)  v = mq ? (v + 1.0f / (float)g_cnt[q]) : 1.0f;
    g_A[idx] = v;
}

// ---------------- standalone potf2 for the first diagonal tile -------------
__global__ void k_potf2_first() {
    __shared__ float S[64][65];
    __shared__ float buf[2][64];
    __shared__ float ds[64];
    int tid = threadIdx.x;   // 256
    for (int i = tid; i < 64 * 64; i += 256)
        S[i >> 6][i & 63] = g_A[(size_t)(i >> 6) * Qq + (i & 63)];
    __syncthreads();
    potf2_core(S, buf, ds, g_A, 0);
}

// ---------------- panel trsm: rows kb*64+64 .. Qq (incl. rhs row) -----------
// Staged through shared for coalesced global access. 256 rows / block.
__global__ void k_trsm(int kb) {
    __shared__ float Ld[64][65];
    __shared__ float stage[64][65];
    __shared__ float rd[64];
    int tid = threadIdx.x;   // 256
    const float* Ab = g_A + (size_t)(kb * NB) * Qq + kb * NB;
    for (int i = tid; i < 64 * 64; i += 256)
        Ld[i >> 6][i & 63] = Ab[(size_t)(i >> 6) * Qq + (i & 63)];
    __syncthreads();
    if (tid < 64) rd[tid] = 1.0f / Ld[tid][tid];

    int row0 = kb * NB + NB + blockIdx.x * 256;
    float x[64];
    // staged coalesced load: 4 chunks of 64 rows
    for (int ch = 0; ch < 4; ch++) {
        int rb = row0 + ch * 64;
        __syncthreads();
        for (int i = tid; i < 64 * 64; i += 256) {
            int rr = i >> 6, cc = i & 63;
            int grow = rb + rr;
            stage[rr][cc] = (grow <= Qq)
                ? g_A[(size_t)grow * Qq + kb * NB + cc] : 0.0f;
        }
        __syncthreads();
        if ((tid >> 6) == ch) {
            int rr = tid & 63;
#pragma unroll
            for (int c = 0; c < 64; c++) x[c] = stage[rr][c];
        }
    }
    __syncthreads();
    // forward substitution against L11^T (per-row, registers)
#pragma unroll
    for (int c = 0; c < 64; c++) {
        float v = x[c];
#pragma unroll
        for (int p = 0; p < c; p++) v -= x[p] * Ld[c][p];
        x[c] = v * rd[c];
    }
    // staged coalesced store
    for (int ch = 0; ch < 4; ch++) {
        if ((tid >> 6) == ch) {
            int rr = tid & 63;
#pragma unroll
            for (int c = 0; c < 64; c++) stage[rr][c] = x[c];
        }
        __syncthreads();
        int rb = row0 + ch * 64;
        for (int i = tid; i < 64 * 64; i += 256) {
            int rr = i >> 6, cc = i & 63;
            int grow = rb + rr;
            if (grow <= Qq)
                g_A[(size_t)grow * Qq + kb * NB + cc] = stage[rr][cc];
        }
        __syncthreads();
    }
}

// ---------------- trailing syrk, fused with potf2 of next diagonal tile -----
// bx in [kb+1 .. NP] (bx==NP is the rhs-row tile), by in [kb+1 .. NP-1].
__global__ void k_syrk(int kb) {
    int nt0 = kb + 1;
    int bx = blockIdx.x + nt0;
    int by = blockIdx.y + nt0;
    if (by > bx) return;
    bool special = (bx == nt0) && (by == nt0);
    __shared__ float Pa[64][65];
    __shared__ float Pb[64][65];
    __shared__ float bcbuf[2][64];
    __shared__ float ds[64];
    int tid = threadIdx.x;  // 256

    const float* baseA = g_A + (size_t)(bx * 64) * Qq + (size_t)kb * NB;
    for (int i = tid; i < 64 * 64; i += 256) {
        int r = i >> 6, c = i & 63;
        int grow = bx * 64 + r;
        Pa[r][c] = (grow <= Qq) ? baseA[(size_t)r * Qq + c] : 0.0f;
    }
    if (special) {
        // Pb holds the current diagonal tile values (to be updated + factored)
        const float* Cd = g_A + (size_t)(bx * 64) * Qq + (size_t)by * 64;
        for (int i = tid; i < 64 * 64; i += 256) {
            int r = i >> 6, c = i & 63;
            Pb[r][c] = Cd[(size_t)r * Qq + c];
        }
    } else {
        const float* baseB = g_A + (size_t)(by * 64) * Qq + (size_t)kb * NB;
        for (int i = tid; i < 64 * 64; i += 256) {
            int r = i >> 6, c = i & 63;
            Pb[r][c] = baseB[(size_t)r * Qq + c];
        }
    }
    __syncthreads();

    int ty = tid >> 4, tx = tid & 15;   // 16x16 threads, 4x4 micro-tile
    float (*Bs)[65] = special ? Pa : Pb;
    float acc[4][4];
#pragma unroll
    for (int i = 0; i < 4; i++)
#pragma unroll
        for (int j = 0; j < 4; j++) acc[i][j] = 0.0f;
#pragma unroll 8
    for (int k = 0; k < 64; k++) {
        float a0 = Pa[ty * 4 + 0][k], a1 = Pa[ty * 4 + 1][k];
        float a2 = Pa[ty * 4 + 2][k], a3 = Pa[ty * 4 + 3][k];
        float b0 = Bs[tx * 4 + 0][k], b1 = Bs[tx * 4 + 1][k];
        float b2 = Bs[tx * 4 + 2][k], b3 = Bs[tx * 4 + 3][k];
        acc[0][0] += a0 * b0; acc[0][1] += a0 * b1; acc[0][2] += a0 * b2; acc[0][3] += a0 * b3;
        acc[1][0] += a1 * b0; acc[1][1] += a1 * b1; acc[1][2] += a1 * b2; acc[1][3] += a1 * b3;
        acc[2][0] += a2 * b0; acc[2][1] += a2 * b1; acc[2][2] += a2 * b2; acc[2][3] += a2 * b3;
        acc[3][0] += a3 * b0; acc[3][1] += a3 * b1; acc[3][2] += a3 * b2; acc[3][3] += a3 * b3;
    }

    if (special) {
        // apply trailing update into shared, then factor the tile in-place
#pragma unroll
        for (int i = 0; i < 4; i++)
#pragma unroll
            for (int j = 0; j < 4; j++) Pb[ty * 4 + i][tx * 4 + j] -= acc[i][j];
        __syncthreads();
        potf2_core(Pb, bcbuf, ds,
                   g_A + (size_t)(nt0 * NB) * Qq + nt0 * NB, nt0);
    } else {
        float* C = g_A + (size_t)(bx * 64 + ty * 4) * Qq + (size_t)by * 64 + tx * 4;
#pragma unroll
        for (int i = 0; i < 4; i++) {
            if (bx * 64 + ty * 4 + i <= Qq) {
#pragma unroll
                for (int j = 0; j < 4; j++) C[(size_t)i * Qq + j] -= acc[i][j];
            }
        }
    }
}

// ---------------- final: ||y||^2 + scalar assembly ----------------
__global__ void k_final(const float* __restrict__ se, const float* __restrict__ sb,
                        float* __restrict__ out) {
    __shared__ double sbuf[256];
    int tid = threadIdx.x;  // 256
    double sy2 = 0.0, st2n = 0.0, slogn = 0.0;
    const float* yrow = g_A + (size_t)Qq * Qq;
    for (int q = tid; q < Qq; q += 256) {
        float y = yrow[q];
        sy2 += (double)y * (double)y;
        int c = g_cnt[q];
        if (c > 0) {
            double tq = (double)g_t[q];
            st2n  += tq * tq / (double)c;
            slogn += log((double)c);
        }
    }
    double SY2 = block_reduce_d(sy2, sbuf);
    double ST  = block_reduce_d(st2n, sbuf);
    double SL  = block_reduce_d(slogn, sbuf);
    if (tid == 0) {
        double sumlogL = 0.0;
        for (int i = 0; i < NP; i++) sumlogL += g_logdiag[i];
        double e = (double)se[0], b = (double)sb[0];
        double sig2 = e + b;
        double sy = g_sums[0], sen = g_sums[1], sz2 = g_sums[2];
        double S1 = ST - SY2;
        double mld = 2.0 * sy + 2.0 * sen + (double)Nn * log(sig2) + (double)Nn * log(C2C);
        double quad = sig2 / e * (sz2 - S1);
        double logdetR = (double)Nn * log(e) + SL + 2.0 * sumlogL - (double)Nn * log(sig2);
        double res = mld + quad - sz2 + logdetR;
        out[0] = (float)res;
    }
}

// ---------------- launch ----------------
extern "C" void kernel_launch(void* const* d_in, const int* in_sizes, int n_in,
                              void* d_out, int out_size) {
    const float*     y_true = (const float*)d_in[0];
    const float*     y_pred = (const float*)d_in[1];
    const float*     sig2e  = (const float*)d_in[2];
    const float*     sig2bs = (const float*)d_in[3];
    const float*     ell    = (const float*)d_in[4];
    const float*     dist   = (const float*)d_in[5];
    const long long* Z_idx  = (const long long*)d_in[6];
    float* out = (float*)d_out;

    k_pre<<<1, 1024>>>(y_true, y_pred, sig2e, sig2bs);
    k_acc<<<1, 1024>>>(Z_idx);
    int nbuild = ((Qq + 1) * Qq + 1023) / 1024;
    k_buildA<<<nbuild, 1024>>>(dist, sig2e, sig2bs, ell);

    k_potf2_first<<<1, 256>>>();
    for (int kb = 0; kb < NP; kb++) {
        int m = NP - 1 - kb;
        int rows = m * 64 + 1;                 // panel rows + rhs row
        k_trsm<<<(rows + 255) / 256, 256>>>(kb);
        if (m > 0) {
            dim3 g(m + 1, m);                  // bx: m panel tiles + rhs tile
            k_syrk<<<g, 256>>>(kb);            // fused: factors diag tile kb+1
        }
    }
    k_final<<<1, 256>>>(sig2e, sig2bs, out);
}

// round 6
// speedup vs baseline: 6.9020x; 1.4591x over previous
#include <cuda_runtime.h>
#include <math.h>

// Problem constants
#define Nn   4096
#define Qq   2048
#define LDIM 8192
#define NB   64
#define NP   (Qq/NB)   // 32

#define EULERC 0.5772156649015329
#define CC     0.7796968012336761   // sqrt(6)/pi
#define C2C    0.6079271018540267   // 6/pi^2
#define ZSCALE 16777216.0f          // 2^24 fixed-point scale for deterministic sums

// ---------------- device scratch (static, allocation-free) ----------------
__device__ float  g_zs[Nn];
__device__ double g_sums[3];
__device__ int    g_cnt[Qq];
__device__ unsigned long long g_tsum[Qq];
__device__ float  g_t[Qq];
__device__ float  g_x[Qq];
// (Qq+1) rows x Qq cols: row Qq holds the rhs r, becomes y = L^{-1} r after sweep
__device__ float  g_A[(size_t)(Qq + 1) * Qq];
__device__ double g_logdiag[NP];
// persistent-kernel sync state
__device__ int    g_flag[NP + 1];
__device__ unsigned int g_barcnt;
__device__ volatile unsigned int g_bargen;

// ---------------- helpers ----------------
__device__ __forceinline__ double block_reduce_d(double v, double* sbuf) {
    int t = threadIdx.x;
    sbuf[t] = v;
    __syncthreads();
    for (int s = blockDim.x >> 1; s > 0; s >>= 1) {
        if (t < s) sbuf[t] += sbuf[t + s];
        __syncthreads();
    }
    double r = sbuf[0];
    __syncthreads();
    return r;
}

__device__ __forceinline__ void grid_bar() {
    __syncthreads();
    if (threadIdx.x == 0) {
        __threadfence();
        unsigned gen = g_bargen;
        if (atomicAdd(&g_barcnt, 1u) == gridDim.x - 1u) {
            g_barcnt = 0u;
            __threadfence();
            g_bargen = gen + 1u;
        } else {
            while (g_bargen == gen) __nanosleep(64);
            __threadfence();
        }
    }
    __syncthreads();
}

// 64x64 Cholesky of tile in shared S; L written to gout (ld = Qq; upper
// triangle garbage by design). Raw-column variant.
// 256 threads: tcol = t&63 owns column tcol, trow = t>>6 owns 16 rows.
__device__ void potf2_core(float S[64][65], float buf[2][64], float* ds,
                           float* gout, int logidx) {
    int t = threadIdx.x;
    int tcol = t & 63;
    int rbase = (t >> 6) * 16;
    float c[16];
#pragma unroll
    for (int i = 0; i < 16; i++) c[i] = S[rbase + i][tcol];
    if (tcol == 0) {
#pragma unroll
        for (int i = 0; i < 16; i++) buf[0][rbase + i] = c[i];
    }
    __syncthreads();
    for (int j = 0; j < 64; j++) {
        float* bc = buf[j & 1];
        if (t == 0) ds[j] = bc[j];
        if (tcol > j) {
            float fr = bc[tcol] * __frcp_rn(bc[j]);
#pragma unroll
            for (int i = 0; i < 16; i++) c[i] -= fr * bc[rbase + i];
            if (tcol == j + 1) {
#pragma unroll
                for (int i = 0; i < 16; i++) buf[(j + 1) & 1][rbase + i] = c[i];
            }
        }
        __syncthreads();
    }
    float r = rsqrtf(ds[tcol]);
#pragma unroll
    for (int i = 0; i < 16; i++)
        gout[(size_t)(rbase + i) * Qq + tcol] = c[i] * r;
    if (t < 64) {
        float lg = logf(ds[tcol]);
#pragma unroll
        for (int off = 16; off > 0; off >>= 1)
            lg += __shfl_down_sync(0xffffffffu, lg, off);
        if ((t & 31) == 0) buf[1][t >> 5] = lg;
    }
    __syncthreads();
    if (t == 0)
        g_logdiag[logidx] = 0.5 * ((double)buf[1][0] + (double)buf[1][1]);
    __syncthreads();
}

// ---------------- kernel 1: per-element transform + scalar sums ----------------
__global__ void k_pre(const float* __restrict__ yt, const float* __restrict__ yp,
                      const float* __restrict__ se, const float* __restrict__ sb) {
    __shared__ double sbuf[1024];
    int tid = threadIdx.x;
    float e = se[0], b = sb[0];
    float sig2 = e + b;
    float inv = 1.0f / ((float)CC * sqrtf(sig2));
    double sy = 0.0, sen = 0.0, sz2 = 0.0;
    for (int i = tid; i < Nn; i += 1024) {
        float y  = (yt[i] - yp[i]) * inv + (float)EULERC;
        float en = expf(-y);
        float u  = expf(-en);
        u = fminf(fmaxf(u, 1e-6f), 1.0f - 1e-6f);
        float zs = 1.41421356237309515f * erfinvf(2.0f * u - 1.0f);
        g_zs[i] = zs;
        sy  += (double)y;
        sen += (double)en;
        sz2 += (double)zs * (double)zs;
    }
    double r;
    r = block_reduce_d(sy, sbuf);  if (tid == 0) g_sums[0] = r;
    r = block_reduce_d(sen, sbuf); if (tid == 0) g_sums[1] = r;
    r = block_reduce_d(sz2, sbuf); if (tid == 0) g_sums[2] = r;
}

// ---------------- kernel 2: deterministic group histogram ----------------
__global__ void k_acc(const long long* __restrict__ Z) {
    int tid = threadIdx.x;                             // 1024
    for (int q = tid; q < Qq; q += 1024) { g_cnt[q] = 0; g_tsum[q] = 0ULL; }
    __syncthreads();
    for (int i = tid; i < Nn; i += 1024) {
        int q = ((int)Z[i]) & (Qq - 1);
        long long fx = (long long)llrintf(g_zs[i] * ZSCALE);
        atomicAdd(&g_cnt[q], 1);
        atomicAdd(&g_tsum[q], (unsigned long long)fx);
    }
    __syncthreads();
    for (int q = tid; q < Qq; q += 1024) {
        int c = g_cnt[q];
        float t = (float)((double)(long long)g_tsum[q] / (double)ZSCALE);
        g_t[q] = t;
        g_x[q] = (c > 0) ? (t / (float)c) : 0.0f;
    }
}

// ---------------- kernel 3: build A, plus rhs row Qq ----------
__global__ void k_buildA(const float* __restrict__ dist, const float* __restrict__ se,
                         const float* __restrict__ sb, const float* __restrict__ ell) {
    int idx = blockIdx.x * blockDim.x + threadIdx.x;
    if (idx >= (Qq + 1) * Qq) return;
    int q = idx >> 11;
    int r = idx & (Qq - 1);
    if (q == Qq) {                 // bordered rhs row: r vector
        g_A[idx] = g_x[r];
        return;
    }
    float e = se[0], b = sb[0];
    float inv2l = -1.0f / (2.0f * ell[0]);
    float scale = b / e;
    int mq = (g_cnt[q] > 0);
    int mr = (g_cnt[r] > 0);
    float v = 0.0f;
    if (mq && mr) v = scale * expf(dist[(size_t)q * LDIM + r] * inv2l);
    if (q == r)  v = mq ? (v + 1.0f / (float)g_cnt[q]) : 1.0f;
    g_A[idx] = v;
}

// ---------------- persistent cooperative Cholesky + forward solve ----------------
// Grid = 2 blocks/SM (co-resident). Per step kb: trsm jobs (per panel tile,
// flag-stamped), then syrk jobs (spin on the two tile flags), grid barrier.
__global__ void __launch_bounds__(256, 2) k_chol() {
    __shared__ float sh[8512];
    float (*Pa)[65]  = reinterpret_cast<float(*)[65]>(sh);          // 64x65
    float (*Pb)[65]  = reinterpret_cast<float(*)[65]>(sh + 4160);   // 64x65
    float (*buf2)[64] = reinterpret_cast<float(*)[64]>(sh + 8320);  // 2x64
    float* ds = sh + 8448;                                          // 64
    int tid = threadIdx.x;
    int bid = blockIdx.x;
    int nblocks = gridDim.x;

    // ---- phase 0: reset flags; factor tile (0,0) ----
    if (bid == 1 || nblocks == 1) {
        for (int i = tid; i <= NP; i += 256) g_flag[i] = 0;
    }
    if (bid == 0) {
        for (int i = tid; i < 4096; i += 256)
            Pa[i >> 6][i & 63] = __ldcg(&g_A[(size_t)(i >> 6) * Qq + (i & 63)]);
        __syncthreads();
        potf2_core(Pa, buf2, ds, g_A, 0);
    }
    grid_bar();

    for (int kb = 0; kb < NP; kb++) {
        int nt0 = kb + 1;
        int m = NP - 1 - kb;
        int ntr = m + 1;                            // panel tiles incl. rhs tile
        int nsy = (m + 1) * (m + 2) / 2 - 1;        // syrk tiles incl. special

        // ---- trsm jobs ----
        if (bid < ntr) {
            // hoisted: diag L tile + reciprocal diagonal
            const float* Ab = g_A + (size_t)(kb * NB) * Qq + kb * NB;
            for (int i = tid; i < 4096; i += 256)
                Pa[i >> 6][i & 63] = __ldcg(&Ab[(size_t)(i >> 6) * Qq + (i & 63)]);
            __syncthreads();
            if (tid < 64) buf2[0][tid] = __frcp_rn(Pa[tid][tid]);
            __syncthreads();
            for (int job = bid; job < ntr; job += nblocks) {
                int bx = nt0 + job;
                for (int i = tid; i < 4096; i += 256) {
                    int grow = bx * 64 + (i >> 6);
                    Pb[i >> 6][i & 63] = (grow <= Qq)
                        ? __ldcg(&g_A[(size_t)grow * Qq + kb * NB + (i & 63)]) : 0.0f;
                }
                __syncthreads();
                if (tid < 64) {
                    float x[64];
#pragma unroll
                    for (int c = 0; c < 64; c++) x[c] = Pb[tid][c];
#pragma unroll
                    for (int c = 0; c < 64; c++) {
                        float a0 = 0.f, a1 = 0.f, a2 = 0.f, a3 = 0.f;
#pragma unroll
                        for (int p = 0; p < c; p += 4) {
                            a0 += x[p] * Pa[c][p];
                            if (p + 1 < c) a1 += x[p + 1] * Pa[c][p + 1];
                            if (p + 2 < c) a2 += x[p + 2] * Pa[c][p + 2];
                            if (p + 3 < c) a3 += x[p + 3] * Pa[c][p + 3];
                        }
                        x[c] = (x[c] - ((a0 + a1) + (a2 + a3))) * buf2[0][c];
                    }
#pragma unroll
                    for (int c = 0; c < 64; c++) Pb[tid][c] = x[c];
                }
                __syncthreads();
                for (int i = tid; i < 4096; i += 256) {
                    int grow = bx * 64 + (i >> 6);
                    if (grow <= Qq)
                        g_A[(size_t)grow * Qq + kb * NB + (i & 63)] = Pb[i >> 6][i & 63];
                }
                __syncthreads();
                if (tid == 0) {
                    __threadfence();
                    atomicExch(&g_flag[bx], nt0);
                }
                __syncthreads();
            }
        }

        // ---- syrk jobs (special job 0 fuses potf2 of tile nt0) ----
        for (int job = bid; job < nsy; job += nblocks) {
            int t2 = job, by = nt0, len = m + 1;
            while (t2 >= len) { t2 -= len; by++; len--; }
            int bx = by + t2;
            bool special = (bx == nt0) && (by == nt0);

            if (tid == 0) {
                while (atomicAdd(&g_flag[bx], 0) != nt0) __nanosleep(32);
                while (atomicAdd(&g_flag[by], 0) != nt0) __nanosleep(32);
                __threadfence();
            }
            __syncthreads();

            const float* baseA = g_A + (size_t)(bx * 64) * Qq + (size_t)kb * NB;
            for (int i = tid; i < 4096; i += 256) {
                int r = i >> 6, c = i & 63;
                int grow = bx * 64 + r;
                Pa[r][c] = (grow <= Qq) ? __ldcg(&baseA[(size_t)r * Qq + c]) : 0.0f;
            }
            if (special) {
                const float* Cd = g_A + (size_t)(bx * 64) * Qq + (size_t)by * 64;
                for (int i = tid; i < 4096; i += 256) {
                    int r = i >> 6, c = i & 63;
                    Pb[r][c] = __ldcg(&Cd[(size_t)r * Qq + c]);
                }
            } else {
                const float* baseB = g_A + (size_t)(by * 64) * Qq + (size_t)kb * NB;
                for (int i = tid; i < 4096; i += 256) {
                    int r = i >> 6, c = i & 63;
                    Pb[r][c] = __ldcg(&baseB[(size_t)r * Qq + c]);
                }
            }
            __syncthreads();

            int ty = tid >> 4, tx = tid & 15;
            float (*Bs)[65] = special ? Pa : Pb;
            float acc[4][4];
#pragma unroll
            for (int i = 0; i < 4; i++)
#pragma unroll
                for (int j = 0; j < 4; j++) acc[i][j] = 0.0f;
#pragma unroll 8
            for (int k = 0; k < 64; k++) {
                float a0 = Pa[ty * 4 + 0][k], a1 = Pa[ty * 4 + 1][k];
                float a2 = Pa[ty * 4 + 2][k], a3 = Pa[ty * 4 + 3][k];
                float b0 = Bs[tx * 4 + 0][k], b1 = Bs[tx * 4 + 1][k];
                float b2 = Bs[tx * 4 + 2][k], b3 = Bs[tx * 4 + 3][k];
                acc[0][0] += a0 * b0; acc[0][1] += a0 * b1; acc[0][2] += a0 * b2; acc[0][3] += a0 * b3;
                acc[1][0] += a1 * b0; acc[1][1] += a1 * b1; acc[1][2] += a1 * b2; acc[1][3] += a1 * b3;
                acc[2][0] += a2 * b0; acc[2][1] += a2 * b1; acc[2][2] += a2 * b2; acc[2][3] += a2 * b3;
                acc[3][0] += a3 * b0; acc[3][1] += a3 * b1; acc[3][2] += a3 * b2; acc[3][3] += a3 * b3;
            }

            if (special) {
#pragma unroll
                for (int i = 0; i < 4; i++)
#pragma unroll
                    for (int j = 0; j < 4; j++) Pb[ty * 4 + i][tx * 4 + j] -= acc[i][j];
                __syncthreads();
                potf2_core(Pb, buf2, ds,
                           g_A + (size_t)(nt0 * NB) * Qq + nt0 * NB, nt0);
            } else {
                float* C = g_A + (size_t)(bx * 64 + ty * 4) * Qq + (size_t)by * 64 + tx * 4;
#pragma unroll
                for (int i = 0; i < 4; i++) {
                    if (bx * 64 + ty * 4 + i <= Qq) {
#pragma unroll
                        for (int j = 0; j < 4; j++) C[(size_t)i * Qq + j] -= acc[i][j];
                    }
                }
            }
            __syncthreads();
        }

        grid_bar();
    }
}

// ---------------- final: ||y||^2 + scalar assembly ----------------
__global__ void k_final(const float* __restrict__ se, const float* __restrict__ sb,
                        float* __restrict__ out) {
    __shared__ double sbuf[256];
    int tid = threadIdx.x;  // 256
    double sy2 = 0.0, st2n = 0.0, slogn = 0.0;
    const float* yrow = g_A + (size_t)Qq * Qq;
    for (int q = tid; q < Qq; q += 256) {
        float y = yrow[q];
        sy2 += (double)y * (double)y;
        int c = g_cnt[q];
        if (c > 0) {
            double tq = (double)g_t[q];
            st2n  += tq * tq / (double)c;
            slogn += log((double)c);
        }
    }
    double SY2 = block_reduce_d(sy2, sbuf);
    double ST  = block_reduce_d(st2n, sbuf);
    double SL  = block_reduce_d(slogn, sbuf);
    if (tid == 0) {
        double sumlogL = 0.0;
        for (int i = 0; i < NP; i++) sumlogL += g_logdiag[i];
        double e = (double)se[0], b = (double)sb[0];
        double sig2 = e + b;
        double sy = g_sums[0], sen = g_sums[1], sz2 = g_sums[2];
        double S1 = ST - SY2;
        double mld = 2.0 * sy + 2.0 * sen + (double)Nn * log(sig2) + (double)Nn * log(C2C);
        double quad = sig2 / e * (sz2 - S1);
        double logdetR = (double)Nn * log(e) + SL + 2.0 * sumlogL - (double)Nn * log(sig2);
        double res = mld + quad - sz2 + logdetR;
        out[0] = (float)res;
    }
}

// ---------------- launch ----------------
extern "C" void kernel_launch(void* const* d_in, const int* in_sizes, int n_in,
                              void* d_out, int out_size) {
    const float*     y_true = (const float*)d_in[0];
    const float*     y_pred = (const float*)d_in[1];
    const float*     sig2e  = (const float*)d_in[2];
    const float*     sig2bs = (const float*)d_in[3];
    const float*     ell    = (const float*)d_in[4];
    const float*     dist   = (const float*)d_in[5];
    const long long* Z_idx  = (const long long*)d_in[6];
    float* out = (float*)d_out;

    int nsm = 0;
    cudaDeviceGetAttribute(&nsm, cudaDevAttrMultiProcessorCount, 0);
    if (nsm <= 0) nsm = 148;
    int nblocks = 2 * nsm;   // guaranteed co-resident via __launch_bounds__(256,2)

    k_pre<<<1, 1024>>>(y_true, y_pred, sig2e, sig2bs);
    k_acc<<<1, 1024>>>(Z_idx);
    int nbuild = ((Qq + 1) * Qq + 1023) / 1024;
    k_buildA<<<nbuild, 1024>>>(dist, sig2e, sig2bs, ell);

    k_chol<<<nblocks, 256>>>();
    k_final<<<1, 256>>>(sig2e, sig2bs, out);
}

// round 7
// speedup vs baseline: 7.7697x; 1.1257x over previous
#include <cuda_runtime.h>
#include <math.h>

// Problem constants
#define Nn   4096
#define Qq   2048
#define LDIM 8192
#define NB   64
#define NP   (Qq/NB)   // 32

#define EULERC 0.5772156649015329
#define CC     0.7796968012336761   // sqrt(6)/pi
#define C2C    0.6079271018540267   // 6/pi^2
#define ZSCALE 16777216.0f          // 2^24 fixed-point scale for deterministic sums

// ---------------- device scratch (static, allocation-free) ----------------
__device__ float  g_zs[Nn];
__device__ double g_sums[3];
__device__ int    g_cnt[Qq];
__device__ unsigned long long g_tsum[Qq];
__device__ float  g_t[Qq];
__device__ float  g_x[Qq];
// (Qq+1) rows x Qq cols: row Qq holds the rhs r, becomes y = L^{-1} r after sweep
__device__ float  g_A[(size_t)(Qq + 1) * Qq];
__device__ double g_logdiag[NP];
// dataflow flags
__device__ int    g_fL;                   // L(kb) published  <=> g_fL >= kb+1
__device__ int    g_ftr[NP + 1];          // trsm of tile bx done for step kb <=> == kb+1
__device__ int    g_gen[(NP + 1) * NP];   // #syrk updates applied to tile (bx,by)

// ---------------- helpers ----------------
__device__ __forceinline__ double block_reduce_d(double v, double* sbuf) {
    int t = threadIdx.x;
    sbuf[t] = v;
    __syncthreads();
    for (int s = blockDim.x >> 1; s > 0; s >>= 1) {
        if (t < s) sbuf[t] += sbuf[t + s];
        __syncthreads();
    }
    double r = sbuf[0];
    __syncthreads();
    return r;
}

__device__ __forceinline__ void wait_eq(int* p, int v) {
    if (threadIdx.x == 0) {
        while (atomicAdd(p, 0) != v) __nanosleep(100);
        __threadfence();
    }
    __syncthreads();
}
__device__ __forceinline__ void wait_ge(int* p, int v) {
    if (threadIdx.x == 0) {
        while (atomicAdd(p, 0) < v) __nanosleep(100);
        __threadfence();
    }
    __syncthreads();
}
__device__ __forceinline__ void publish(int* p, int v) {
    __threadfence();           // every thread fences its own stores
    __syncthreads();
    if (threadIdx.x == 0) atomicExch(p, v);
}

// 64x64 Cholesky of tile in shared S; L written to gout (ld=Qq; upper triangle
// garbage by design) AND written back into S (scaled). Raw-column variant.
__device__ void potf2_core(float S[64][65], float buf[2][64], float* ds,
                           float* gout, int logidx) {
    int t = threadIdx.x;
    int tcol = t & 63;
    int rbase = (t >> 6) * 16;
    float c[16];
#pragma unroll
    for (int i = 0; i < 16; i++) c[i] = S[rbase + i][tcol];
    if (tcol == 0) {
#pragma unroll
        for (int i = 0; i < 16; i++) buf[0][rbase + i] = c[i];
    }
    __syncthreads();
    for (int j = 0; j < 64; j++) {
        float* bc = buf[j & 1];
        if (t == 0) ds[j] = bc[j];
        if (tcol > j) {
            float fr = bc[tcol] * __frcp_rn(bc[j]);
#pragma unroll
            for (int i = 0; i < 16; i++) c[i] -= fr * bc[rbase + i];
            if (tcol == j + 1) {
#pragma unroll
                for (int i = 0; i < 16; i++) buf[(j + 1) & 1][rbase + i] = c[i];
            }
        }
        __syncthreads();
    }
    float r = rsqrtf(ds[tcol]);
#pragma unroll
    for (int i = 0; i < 16; i++) {
        float v = c[i] * r;
        gout[(size_t)(rbase + i) * Qq + tcol] = v;
        S[rbase + i][tcol] = v;           // shared writeback for local reuse
    }
    if (t < 64) {
        float lg = logf(ds[tcol]);
#pragma unroll
        for (int off = 16; off > 0; off >>= 1)
            lg += __shfl_down_sync(0xffffffffu, lg, off);
        if ((t & 31) == 0) buf[1][t >> 5] = lg;
    }
    __syncthreads();
    if (t == 0)
        g_logdiag[logidx] = 0.5 * ((double)buf[1][0] + (double)buf[1][1]);
    __syncthreads();
}

// forward substitution of 64 rows in X against lower-tri Ld (rd = 1/diag)
__device__ __forceinline__ void trsm64(float (*Ld)[65], float (*X)[65],
                                       const float* rd) {
    int tid = threadIdx.x;
    if (tid < 64) {
        float x[64];
#pragma unroll
        for (int c = 0; c < 64; c++) x[c] = X[tid][c];
#pragma unroll
        for (int c = 0; c < 64; c++) {
            float a0 = 0.f, a1 = 0.f, a2 = 0.f, a3 = 0.f;
#pragma unroll
            for (int p = 0; p < c; p += 4) {
                a0 += x[p] * Ld[c][p];
                if (p + 1 < c) a1 += x[p + 1] * Ld[c][p + 1];
                if (p + 2 < c) a2 += x[p + 2] * Ld[c][p + 2];
                if (p + 3 < c) a3 += x[p + 3] * Ld[c][p + 3];
            }
            x[c] = (x[c] - ((a0 + a1) + (a2 + a3))) * rd[c];
        }
#pragma unroll
        for (int c = 0; c < 64; c++) X[tid][c] = x[c];
    }
}

// 64x64x64 A*B^T accumulate: acc[4][4] per thread (16x16 grid of threads)
__device__ __forceinline__ void syrk_acc(float (*Pa)[65], float (*Pb)[65],
                                         float acc[4][4]) {
    int ty = threadIdx.x >> 4, tx = threadIdx.x & 15;
#pragma unroll
    for (int i = 0; i < 4; i++)
#pragma unroll
        for (int j = 0; j < 4; j++) acc[i][j] = 0.0f;
#pragma unroll 8
    for (int k = 0; k < 64; k++) {
        float a0 = Pa[ty * 4 + 0][k], a1 = Pa[ty * 4 + 1][k];
        float a2 = Pa[ty * 4 + 2][k], a3 = Pa[ty * 4 + 3][k];
        float b0 = Pb[tx * 4 + 0][k], b1 = Pb[tx * 4 + 1][k];
        float b2 = Pb[tx * 4 + 2][k], b3 = Pb[tx * 4 + 3][k];
        acc[0][0] += a0 * b0; acc[0][1] += a0 * b1; acc[0][2] += a0 * b2; acc[0][3] += a0 * b3;
        acc[1][0] += a1 * b0; acc[1][1] += a1 * b1; acc[1][2] += a1 * b2; acc[1][3] += a1 * b3;
        acc[2][0] += a2 * b0; acc[2][1] += a2 * b1; acc[2][2] += a2 * b2; acc[2][3] += a2 * b3;
        acc[3][0] += a3 * b0; acc[3][1] += a3 * b1; acc[3][2] += a3 * b2; acc[3][3] += a3 * b3;
    }
}

// ---------------- kernel 1: per-element transform + scalar sums ----------------
__global__ void k_pre(const float* __restrict__ yt, const float* __restrict__ yp,
                      const float* __restrict__ se, const float* __restrict__ sb) {
    __shared__ double sbuf[1024];
    int tid = threadIdx.x;
    float e = se[0], b = sb[0];
    float sig2 = e + b;
    float inv = 1.0f / ((float)CC * sqrtf(sig2));
    double sy = 0.0, sen = 0.0, sz2 = 0.0;
    for (int i = tid; i < Nn; i += 1024) {
        float y  = (yt[i] - yp[i]) * inv + (float)EULERC;
        float en = expf(-y);
        float u  = expf(-en);
        u = fminf(fmaxf(u, 1e-6f), 1.0f - 1e-6f);
        float zs = 1.41421356237309515f * erfinvf(2.0f * u - 1.0f);
        g_zs[i] = zs;
        sy  += (double)y;
        sen += (double)en;
        sz2 += (double)zs * (double)zs;
    }
    double r;
    r = block_reduce_d(sy, sbuf);  if (tid == 0) g_sums[0] = r;
    r = block_reduce_d(sen, sbuf); if (tid == 0) g_sums[1] = r;
    r = block_reduce_d(sz2, sbuf); if (tid == 0) g_sums[2] = r;
}

// ---------------- kernel 2: histogram + flag reset ----------------
__global__ void k_acc(const long long* __restrict__ Z) {
    int tid = threadIdx.x;                             // 1024
    for (int q = tid; q < Qq; q += 1024) { g_cnt[q] = 0; g_tsum[q] = 0ULL; }
    for (int i = tid; i < (NP + 1) * NP; i += 1024) g_gen[i] = 0;
    if (tid <= NP) g_ftr[tid] = 0;
    if (tid == 0) g_fL = 0;
    __syncthreads();
    for (int i = tid; i < Nn; i += 1024) {
        int q = ((int)Z[i]) & (Qq - 1);
        long long fx = (long long)llrintf(g_zs[i] * ZSCALE);
        atomicAdd(&g_cnt[q], 1);
        atomicAdd(&g_tsum[q], (unsigned long long)fx);
    }
    __syncthreads();
    for (int q = tid; q < Qq; q += 1024) {
        int c = g_cnt[q];
        float t = (float)((double)(long long)g_tsum[q] / (double)ZSCALE);
        g_t[q] = t;
        g_x[q] = (c > 0) ? (t / (float)c) : 0.0f;
    }
}

// ---------------- kernel 3: build A, plus rhs row Qq ----------
__global__ void k_buildA(const float* __restrict__ dist, const float* __restrict__ se,
                         const float* __restrict__ sb, const float* __restrict__ ell) {
    int idx = blockIdx.x * blockDim.x + threadIdx.x;
    if (idx >= (Qq + 1) * Qq) return;
    int q = idx >> 11;
    int r = idx & (Qq - 1);
    if (q == Qq) { g_A[idx] = g_x[r]; return; }
    float e = se[0], b = sb[0];
    float inv2l = -1.0f / (2.0f * ell[0]);
    float scale = b / e;
    int mq = (g_cnt[q] > 0);
    int mr = (g_cnt[r] > 0);
    float v = 0.0f;
    if (mq && mr) v = scale * expf(dist[(size_t)q * LDIM + r] * inv2l);
    if (q == r)  v = mq ? (v + 1.0f / (float)g_cnt[q]) : 1.0f;
    g_A[idx] = v;
}

// ---------------- persistent dataflow Cholesky + forward solve + final ----------
__global__ void __launch_bounds__(256, 2) k_chol(const float* __restrict__ se,
                                                 const float* __restrict__ sb,
                                                 float* __restrict__ out) {
    __shared__ float sh[8512];
    float (*Pa)[65]   = reinterpret_cast<float(*)[65]>(sh);          // 64x65
    float (*Pb)[65]   = reinterpret_cast<float(*)[65]>(sh + 4160);   // 64x65
    float (*buf2)[64] = reinterpret_cast<float(*)[64]>(sh + 8320);   // 2x64
    float* ds = sh + 8448;                                           // 64
    int tid = threadIdx.x;
    int bid = blockIdx.x;

    if (bid == 0) {
        // ================= critical-chain block =================
        for (int i = tid; i < 4096; i += 256)
            Pa[i >> 6][i & 63] = __ldcg(&g_A[(size_t)(i >> 6) * Qq + (i & 63)]);
        __syncthreads();
        potf2_core(Pa, buf2, ds, g_A, 0);          // Pa now holds L(0)
        publish(&g_fL, 1);

        for (int kb = 0; kb < NP; kb++) {
            int nt0 = kb + 1;
            // ---- trsm of the critical tile (nt0, col kb); L(kb) is in Pa ----
            wait_eq(&g_gen[nt0 * NP + kb], kb);
            for (int i = tid; i < 4096; i += 256) {
                int grow = nt0 * 64 + (i >> 6);
                Pb[i >> 6][i & 63] = (grow <= Qq)
                    ? __ldcg(&g_A[(size_t)grow * Qq + (size_t)kb * NB + (i & 63)]) : 0.0f;
            }
            __syncthreads();
            if (tid < 64) buf2[0][tid] = __frcp_rn(Pa[tid][tid]);
            __syncthreads();
            trsm64(Pa, Pb, buf2[0]);
            __syncthreads();
            for (int i = tid; i < 4096; i += 256) {
                int grow = nt0 * 64 + (i >> 6);
                if (grow <= Qq)
                    g_A[(size_t)grow * Qq + (size_t)kb * NB + (i & 63)] = Pb[i >> 6][i & 63];
            }
            publish(&g_ftr[nt0], kb + 1);

            if (nt0 < NP) {
                // ---- special: update + factor diag tile (nt0,nt0); X is in Pb ----
                wait_eq(&g_gen[nt0 * NP + nt0], kb);
                const float* Cd = g_A + (size_t)(nt0 * 64) * Qq + (size_t)nt0 * 64;
                for (int i = tid; i < 4096; i += 256)
                    Pa[i >> 6][i & 63] = __ldcg(&Cd[(size_t)(i >> 6) * Qq + (i & 63)]);
                __syncthreads();
                float acc[4][4];
                syrk_acc(Pb, Pb, acc);
                int ty = tid >> 4, tx = tid & 15;
#pragma unroll
                for (int i = 0; i < 4; i++)
#pragma unroll
                    for (int j = 0; j < 4; j++)
                        Pa[ty * 4 + i][tx * 4 + j] -= acc[i][j];
                __syncthreads();
                potf2_core(Pa, buf2, ds,
                           g_A + (size_t)(nt0 * NB) * Qq + nt0 * NB, nt0);
                publish(&g_fL, nt0 + 1);           // Pa now holds L(nt0)
            }
        }

        // ================= final reduction (y row fully solved) =================
        double* sbuf = reinterpret_cast<double*>(sh);
        double sy2 = 0.0, st2n = 0.0, slogn = 0.0;
        const float* yrow = g_A + (size_t)Qq * Qq;
        for (int q = tid; q < Qq; q += 256) {
            float y = __ldcg(&yrow[q]);
            sy2 += (double)y * (double)y;
            int c = g_cnt[q];
            if (c > 0) {
                double tq = (double)g_t[q];
                st2n  += tq * tq / (double)c;
                slogn += log((double)c);
            }
        }
        double SY2 = block_reduce_d(sy2, sbuf);
        double ST  = block_reduce_d(st2n, sbuf);
        double SL  = block_reduce_d(slogn, sbuf);
        if (tid == 0) {
            double sumlogL = 0.0;
            for (int i = 0; i < NP; i++) sumlogL += g_logdiag[i];
            double e = (double)se[0], b = (double)sb[0];
            double sig2 = e + b;
            double sy = g_sums[0], sen = g_sums[1], sz2 = g_sums[2];
            double S1 = ST - SY2;
            double mld = 2.0 * sy + 2.0 * sen + (double)Nn * log(sig2) + (double)Nn * log(C2C);
            double quad = sig2 / e * (sz2 - S1);
            double logdetR = (double)Nn * log(e) + SL + 2.0 * sumlogL - (double)Nn * log(sig2);
            out[0] = (float)(mld + quad - sz2 + logdetR);
        }
        return;
    }

    // ================= worker blocks =================
    int w = bid - 1;
    int W = gridDim.x - 1;
    for (int kb = 0; kb < NP; kb++) {
        int nt0 = kb + 1;
        int m = NP - 1 - kb;
        int nsy = (m + 1) * (m + 2) / 2 - 1;
        int njobs = m + (nsy > 0 ? nsy - 1 : 0);
        for (int job = w; job < njobs; job += W) {
            if (job < m) {
                // ---- trsm of tile bx = nt0+1+job against L(kb) ----
                int bx = nt0 + 1 + job;
                wait_ge(&g_fL, kb + 1);
                const float* Lk = g_A + (size_t)(kb * NB) * Qq + kb * NB;
                for (int i = tid; i < 4096; i += 256)
                    Pa[i >> 6][i & 63] = __ldcg(&Lk[(size_t)(i >> 6) * Qq + (i & 63)]);
                __syncthreads();
                if (tid < 64) buf2[0][tid] = __frcp_rn(Pa[tid][tid]);
                wait_eq(&g_gen[bx * NP + kb], kb);
                for (int i = tid; i < 4096; i += 256) {
                    int grow = bx * 64 + (i >> 6);
                    Pb[i >> 6][i & 63] = (grow <= Qq)
                        ? __ldcg(&g_A[(size_t)grow * Qq + (size_t)kb * NB + (i & 63)]) : 0.0f;
                }
                __syncthreads();
                trsm64(Pa, Pb, buf2[0]);
                __syncthreads();
                for (int i = tid; i < 4096; i += 256) {
                    int grow = bx * 64 + (i >> 6);
                    if (grow <= Qq)
                        g_A[(size_t)grow * Qq + (size_t)kb * NB + (i & 63)] = Pb[i >> 6][i & 63];
                }
                publish(&g_ftr[bx], kb + 1);
            } else {
                // ---- regular syrk tile ----
                int j = job - m + 1;                 // 1..nsy-1 (0 is special)
                int t2 = j, by = nt0, len = m + 1;
                while (t2 >= len) { t2 -= len; by++; len--; }
                int bx = by + t2;
                wait_ge(&g_ftr[bx], kb + 1);
                wait_ge(&g_ftr[by], kb + 1);
                wait_eq(&g_gen[bx * NP + by], kb);
                const float* baseA = g_A + (size_t)(bx * 64) * Qq + (size_t)kb * NB;
                const float* baseB = g_A + (size_t)(by * 64) * Qq + (size_t)kb * NB;
                for (int i = tid; i < 4096; i += 256) {
                    int r = i >> 6, c = i & 63;
                    int grow = bx * 64 + r;
                    Pa[r][c] = (grow <= Qq) ? __ldcg(&baseA[(size_t)r * Qq + c]) : 0.0f;
                    Pb[r][c] = __ldcg(&baseB[(size_t)r * Qq + c]);
                }
                __syncthreads();
                float acc[4][4];
                syrk_acc(Pa, Pb, acc);
                int ty = tid >> 4, tx = tid & 15;
                float* C = g_A + (size_t)(bx * 64 + ty * 4) * Qq + (size_t)by * 64 + tx * 4;
#pragma unroll
                for (int i = 0; i < 4; i++) {
                    if (bx * 64 + ty * 4 + i <= Qq) {
#pragma unroll
                        for (int jj = 0; jj < 4; jj++)
                            C[(size_t)i * Qq + jj] = __ldcg(&C[(size_t)i * Qq + jj]) - acc[i][jj];
                    }
                }
                publish(&g_gen[bx * NP + by], kb + 1);
            }
        }
    }
}

// ---------------- launch ----------------
extern "C" void kernel_launch(void* const* d_in, const int* in_sizes, int n_in,
                              void* d_out, int out_size) {
    const float*     y_true = (const float*)d_in[0];
    const float*     y_pred = (const float*)d_in[1];
    const float*     sig2e  = (const float*)d_in[2];
    const float*     sig2bs = (const float*)d_in[3];
    const float*     ell    = (const float*)d_in[4];
    const float*     dist   = (const float*)d_in[5];
    const long long* Z_idx  = (const long long*)d_in[6];
    float* out = (float*)d_out;

    int nsm = 0;
    cudaDeviceGetAttribute(&nsm, cudaDevAttrMultiProcessorCount, 0);
    if (nsm <= 0) nsm = 148;
    int nblocks = 2 * nsm;   // co-resident via __launch_bounds__(256,2)

    k_pre<<<1, 1024>>>(y_true, y_pred, sig2e, sig2bs);
    k_acc<<<1, 1024>>>(Z_idx);
    int nbuild = ((Qq + 1) * Qq + 1023) / 1024;
    k_buildA<<<nbuild, 1024>>>(dist, sig2e, sig2bs, ell);

    k_chol<<<nblocks, 256>>>(sig2e, sig2bs, out);
}